// round 2
// baseline (speedup 1.0000x reference)
#include <cuda_runtime.h>
#include <math.h>

// ---------------- problem constants ----------------
#define N_TX   100000
#define N_ADDR 200000
#define NE     400000
#define F_TX   165
#define F_ADDR 64
#define HDIM   64
#define HD     256
#define LN_EPS 1e-5f
#define NEG_SLOPE 0.2f

// ---------------- scratch (device globals; no cudaMalloc allowed) ----------------
__device__ float g_htx64[(size_t)N_TX * HDIM];
__device__ float g_haddr64[(size_t)N_ADDR * HDIM];
__device__ float g_hs_at[(size_t)N_ADDR * HD];   // addr projected by W_at
__device__ float g_hd_at[(size_t)N_TX * HD];     // tx projected by W_at
__device__ float g_hs_ta[(size_t)N_TX * HD];     // tx projected by W_ta
__device__ float g_hd_ta[(size_t)N_ADDR * HD];   // addr projected by W_ta
__device__ float g_agg_tx[(size_t)N_TX * HD];
__device__ float g_agg_addr[(size_t)N_ADDR * HD];
__device__ float g_htx[(size_t)N_TX * HD];
__device__ float g_haddr[(size_t)N_ADDR * HD];
__device__ float4 g_als_at[N_ADDR];
__device__ float4 g_ald_at[N_TX];
__device__ float4 g_als_ta[N_TX];
__device__ float4 g_ald_ta[N_ADDR];
__device__ float4 g_al_at[NE];
__device__ float4 g_al_ta[NE];
__device__ int g_cnt_tx[N_TX];
__device__ int g_cnt_addr[N_ADDR];
__device__ int g_rp_at[N_TX + 1];
__device__ int g_rp_ta[N_ADDR + 1];
__device__ int g_cur_tx[N_TX];
__device__ int g_cur_addr[N_ADDR];
__device__ int g_eidx_at[NE];
__device__ int g_eidx_ta[NE];

// ---------------- SGEMM: C[M,N] = A[M,K] @ B[K,N] (+bias) ----------------
#define BM 128
#define BN 128
#define BK 8
#define TM 8
#define TN 8

__global__ __launch_bounds__(256)
void hg_sgemm(const float* __restrict__ A, const float* __restrict__ B,
              const float* __restrict__ bias, float* __restrict__ C,
              int M, int N, int K) {
    __shared__ float As[BK][BM];
    __shared__ float Bs[BK][BN];
    int tid = threadIdx.x;
    int row0 = blockIdx.y * BM, col0 = blockIdx.x * BN;
    int tx = tid & 15, ty = tid >> 4;
    int am = tid >> 1, ak = (tid & 1) * 4;
    int bk = tid >> 5, bn = (tid & 31) * 4;
    float acc[TM][TN];
    #pragma unroll
    for (int i = 0; i < TM; i++)
        #pragma unroll
        for (int j = 0; j < TN; j++) acc[i][j] = 0.f;

    bool k4 = ((K & 3) == 0);
    for (int k0 = 0; k0 < K; k0 += BK) {
        // A tile -> As[k][m] (transposed)
        {
            int gr = row0 + am;
            if (k4) {
                float4 av = make_float4(0.f, 0.f, 0.f, 0.f);
                int gk = k0 + ak;
                if (gr < M && gk < K)
                    av = *(const float4*)(A + (long)gr * K + gk);
                As[ak + 0][am] = av.x;
                As[ak + 1][am] = av.y;
                As[ak + 2][am] = av.z;
                As[ak + 3][am] = av.w;
            } else {
                #pragma unroll
                for (int i = 0; i < 4; i++) {
                    int kk = ak + i, gk = k0 + kk;
                    As[kk][am] = (gr < M && gk < K) ? A[(long)gr * K + gk] : 0.f;
                }
            }
        }
        // B tile
        {
            int gk = k0 + bk, gn = col0 + bn;
            float4 bv = make_float4(0.f, 0.f, 0.f, 0.f);
            if (gk < K && gn < N)   // N is a multiple of 4 in all call sites
                bv = *(const float4*)(B + (long)gk * N + gn);
            *(float4*)&Bs[bk][bn] = bv;
        }
        __syncthreads();
        #pragma unroll
        for (int k = 0; k < BK; k++) {
            float af[TM], bf[TN];
            #pragma unroll
            for (int i = 0; i < TM; i++) af[i] = As[k][ty * TM + i];
            #pragma unroll
            for (int j = 0; j < TN; j++) bf[j] = Bs[k][tx * TN + j];
            #pragma unroll
            for (int i = 0; i < TM; i++)
                #pragma unroll
                for (int j = 0; j < TN; j++) acc[i][j] += af[i] * bf[j];
        }
        __syncthreads();
    }
    #pragma unroll
    for (int i = 0; i < TM; i++) {
        int gr = row0 + ty * TM + i;
        if (gr >= M) continue;
        #pragma unroll
        for (int j = 0; j < TN; j++) {
            int gc = col0 + tx * TN + j;
            if (gc < N) {
                float v = acc[i][j];
                if (bias) v += bias[gc];
                C[(long)gr * N + gc] = v;
            }
        }
    }
}

// ---------------- CSR build ----------------
__global__ void hg_zero2(int* a, int na, int* b, int nb) {
    int i = blockIdx.x * blockDim.x + threadIdx.x;
    if (i < na) a[i] = 0;
    if (i < nb) b[i] = 0;
}

__global__ void hg_count(const int* __restrict__ dst_at, int* cnt_at,
                         const int* __restrict__ dst_ta, int* cnt_ta) {
    int i = blockIdx.x * blockDim.x + threadIdx.x;
    if (i < NE) {
        atomicAdd(&cnt_at[dst_at[i]], 1);
        atomicAdd(&cnt_ta[dst_ta[i]], 1);
    }
}

__global__ void hg_exscan(const int* __restrict__ cnt, int* __restrict__ rp, int n) {
    __shared__ int wsum[32];
    __shared__ int carry;
    int lane = threadIdx.x & 31, wid = threadIdx.x >> 5;
    if (threadIdx.x == 0) { carry = 0; rp[0] = 0; }
    __syncthreads();
    for (int base = 0; base < n; base += 1024) {
        int i = base + threadIdx.x;
        int v = (i < n) ? cnt[i] : 0;
        int s = v;
        #pragma unroll
        for (int o = 1; o < 32; o <<= 1) {
            int t = __shfl_up_sync(0xffffffffu, s, o);
            if (lane >= o) s += t;
        }
        if (lane == 31) wsum[wid] = s;
        __syncthreads();
        if (wid == 0) {
            int w = wsum[lane];
            #pragma unroll
            for (int o = 1; o < 32; o <<= 1) {
                int t = __shfl_up_sync(0xffffffffu, w, o);
                if (lane >= o) w += t;
            }
            wsum[lane] = w;
        }
        __syncthreads();
        int off = carry + (wid ? wsum[wid - 1] : 0);
        if (i < n) rp[i + 1] = off + s;
        __syncthreads();
        if (threadIdx.x == 0) carry += wsum[31];
        __syncthreads();
    }
}

__global__ void hg_fill(const int* __restrict__ dst_at, int* cur_at, int* eidx_at,
                        const int* __restrict__ dst_ta, int* cur_ta, int* eidx_ta) {
    int i = blockIdx.x * blockDim.x + threadIdx.x;
    if (i < NE) {
        int p = atomicAdd(&cur_at[dst_at[i]], 1);
        eidx_at[p] = i;
        int q = atomicAdd(&cur_ta[dst_ta[i]], 1);
        eidx_ta[q] = i;
    }
}

// ---------------- attention node coefficients ----------------
// out[n] = per-head dot(h[n, head*64 : head*64+64], a[head]) ; a laid out flat [256]
__global__ void hg_node_coef(const float* __restrict__ h, const float* __restrict__ a,
                             float4* __restrict__ out, int n) {
    int warp = (blockIdx.x * blockDim.x + threadIdx.x) >> 5;
    int lane = threadIdx.x & 31;
    if (warp >= n) return;
    const float* hp = h + (long)warp * HD;
    float s[4] = {0.f, 0.f, 0.f, 0.f};
    #pragma unroll
    for (int j = 0; j < 8; j++) {
        int c = lane + 32 * j;
        s[j >> 1] += hp[c] * a[c];
    }
    #pragma unroll
    for (int o = 16; o > 0; o >>= 1) {
        s[0] += __shfl_xor_sync(0xffffffffu, s[0], o);
        s[1] += __shfl_xor_sync(0xffffffffu, s[1], o);
        s[2] += __shfl_xor_sync(0xffffffffu, s[2], o);
        s[3] += __shfl_xor_sync(0xffffffffu, s[3], o);
    }
    if (lane == 0) out[warp] = make_float4(s[0], s[1], s[2], s[3]);
}

// ---------------- per-edge attention logits (leaky relu) ----------------
__device__ __forceinline__ float hg_leaky(float v) { return v >= 0.f ? v : NEG_SLOPE * v; }

__global__ void hg_edge_al(const int* __restrict__ src, const int* __restrict__ dst,
                           const float4* __restrict__ als, const float4* __restrict__ ald,
                           float4* __restrict__ al) {
    int i = blockIdx.x * blockDim.x + threadIdx.x;
    if (i >= NE) return;
    float4 s = als[src[i]];
    float4 d = ald[dst[i]];
    float4 r;
    r.x = hg_leaky(s.x + d.x);
    r.y = hg_leaky(s.y + d.y);
    r.z = hg_leaky(s.z + d.z);
    r.w = hg_leaky(s.w + d.w);
    al[i] = r;
}

// ---------------- segment softmax + weighted aggregation (warp per dst node) ----------------
__global__ void hg_gat_agg(const float* __restrict__ hs, const int* __restrict__ src,
                           const float4* __restrict__ al, const int* __restrict__ rp,
                           const int* __restrict__ eidx, float* __restrict__ out, int ndst) {
    int warp = (blockIdx.x * blockDim.x + threadIdx.x) >> 5;
    int lane = threadIdx.x & 31;
    if (warp >= ndst) return;
    int beg = rp[warp], end = rp[warp + 1];
    int c0 = lane * 8;
    float* op = out + (long)warp * HD + c0;
    if (beg == end) {
        *(float4*)op = make_float4(0.f, 0.f, 0.f, 0.f);
        *(float4*)(op + 4) = make_float4(0.f, 0.f, 0.f, 0.f);
        return;
    }
    float m0 = -3.4e38f, m1 = -3.4e38f, m2 = -3.4e38f, m3 = -3.4e38f;
    for (int t = beg; t < end; t++) {
        float4 a = al[eidx[t]];
        m0 = fmaxf(m0, a.x); m1 = fmaxf(m1, a.y);
        m2 = fmaxf(m2, a.z); m3 = fmaxf(m3, a.w);
    }
    float d0 = 0.f, d1 = 0.f, d2 = 0.f, d3 = 0.f;
    for (int t = beg; t < end; t++) {
        float4 a = al[eidx[t]];
        d0 += __expf(a.x - m0); d1 += __expf(a.y - m1);
        d2 += __expf(a.z - m2); d3 += __expf(a.w - m3);
    }
    int hl = lane >> 3;  // 8 consecutive channels -> one head
    float mh = (hl & 2) ? ((hl & 1) ? m3 : m2) : ((hl & 1) ? m1 : m0);
    float dh = (hl & 2) ? ((hl & 1) ? d3 : d2) : ((hl & 1) ? d1 : d0);
    float inv = 1.f / dh;
    float acc[8] = {0.f, 0.f, 0.f, 0.f, 0.f, 0.f, 0.f, 0.f};
    for (int t = beg; t < end; t++) {
        int eid = eidx[t];
        int s = src[eid];
        float4 a = al[eid];
        float av = (hl & 2) ? ((hl & 1) ? a.w : a.z) : ((hl & 1) ? a.y : a.x);
        float alpha = __expf(av - mh) * inv;
        const float4* hp = (const float4*)(hs + (long)s * HD + c0);
        float4 v0 = hp[0], v1 = hp[1];
        acc[0] += alpha * v0.x; acc[1] += alpha * v0.y;
        acc[2] += alpha * v0.z; acc[3] += alpha * v0.w;
        acc[4] += alpha * v1.x; acc[5] += alpha * v1.y;
        acc[6] += alpha * v1.z; acc[7] += alpha * v1.w;
    }
    *(float4*)op = make_float4(acc[0], acc[1], acc[2], acc[3]);
    *(float4*)(op + 4) = make_float4(acc[4], acc[5], acc[6], acc[7]);
}

// ---------------- bias + LayerNorm + (residual) + ELU, in-place h update ----------------
__device__ __forceinline__ float hg_blk_sum256(float v) {
    __shared__ float sh[8];
    int lane = threadIdx.x & 31, wid = threadIdx.x >> 5;
    #pragma unroll
    for (int o = 16; o > 0; o >>= 1) v += __shfl_xor_sync(0xffffffffu, v, o);
    if (lane == 0) sh[wid] = v;
    __syncthreads();
    float r = (wid == 0 && lane < 8) ? sh[lane] : 0.f;
    if (wid == 0) {
        #pragma unroll
        for (int o = 4; o > 0; o >>= 1) r += __shfl_xor_sync(0xffffffffu, r, o);
        if (lane == 0) sh[0] = r;
    }
    __syncthreads();
    r = sh[0];
    __syncthreads();
    return r;
}

__global__ void hg_post_ln(const float* __restrict__ agg, const float* __restrict__ bias,
                           const float* __restrict__ gam, const float* __restrict__ bet,
                           float* __restrict__ h, int residual) {
    long row = blockIdx.x;
    int t = threadIdx.x;
    float v = agg[row * HD + t] + bias[t];
    float mu = hg_blk_sum256(v) * (1.f / HD);
    float d = v - mu;
    float var = hg_blk_sum256(d * d) * (1.f / HD);
    float y = d * rsqrtf(var + LN_EPS) * gam[t] + bet[t];
    if (residual) y += h[row * HD + t];
    h[row * HD + t] = y > 0.f ? y : expm1f(y);
}

// ---------------- mean pooling addr -> tx (warp per tx node) ----------------
__global__ void hg_pool_mean(const float* __restrict__ haddr, const int* __restrict__ src,
                             const int* __restrict__ rp, const int* __restrict__ eidx,
                             float* __restrict__ out, int ndst) {
    int warp = (blockIdx.x * blockDim.x + threadIdx.x) >> 5;
    int lane = threadIdx.x & 31;
    if (warp >= ndst) return;
    int beg = rp[warp], end = rp[warp + 1];
    int c0 = lane * 8;
    float acc[8] = {0.f, 0.f, 0.f, 0.f, 0.f, 0.f, 0.f, 0.f};
    for (int t = beg; t < end; t++) {
        int s = src[eidx[t]];
        const float4* hp = (const float4*)(haddr + (long)s * HD + c0);
        float4 v0 = hp[0], v1 = hp[1];
        acc[0] += v0.x; acc[1] += v0.y; acc[2] += v0.z; acc[3] += v0.w;
        acc[4] += v1.x; acc[5] += v1.y; acc[6] += v1.z; acc[7] += v1.w;
    }
    int deg = end - beg;
    float inv = 1.f / (float)(deg > 0 ? deg : 1);
    float* op = out + (long)warp * HD + c0;
    *(float4*)op = make_float4(acc[0] * inv, acc[1] * inv, acc[2] * inv, acc[3] * inv);
    *(float4*)(op + 4) = make_float4(acc[4] * inv, acc[5] * inv, acc[6] * inv, acc[7] * inv);
}

// ---------------- host launcher ----------------
#define SYMADDR(p, s) do { void* _t = nullptr; cudaGetSymbolAddress(&_t, s); p = (decltype(p))_t; } while (0)

static inline void launch_gemm(const float* A, const float* B, const float* bias,
                               float* C, int M, int N, int K) {
    dim3 grid((N + BN - 1) / BN, (M + BM - 1) / BM);
    hg_sgemm<<<grid, 256>>>(A, B, bias, C, M, N, K);
}

extern "C" void kernel_launch(void* const* d_in, const int* in_sizes, int n_in,
                              void* d_out, int out_size) {
    const float* x_tx      = (const float*)d_in[0];
    const float* x_addr    = (const float*)d_in[1];
    const int*   addr_idx_at = (const int*)d_in[2];
    const int*   tx_idx_at   = (const int*)d_in[3];
    const int*   tx_idx_ta   = (const int*)d_in[4];
    const int*   addr_idx_ta = (const int*)d_in[5];
    const float* w_in_tx   = (const float*)d_in[6];
    const float* b_in_tx   = (const float*)d_in[7];
    const float* w_in_addr = (const float*)d_in[8];
    const float* b_in_addr = (const float*)d_in[9];
    const float* w_at0 = (const float*)d_in[10];
    const float* as_at0 = (const float*)d_in[11];
    const float* ad_at0 = (const float*)d_in[12];
    const float* b_at0 = (const float*)d_in[13];
    const float* w_ta0 = (const float*)d_in[14];
    const float* as_ta0 = (const float*)d_in[15];
    const float* ad_ta0 = (const float*)d_in[16];
    const float* b_ta0 = (const float*)d_in[17];
    const float* w_at1 = (const float*)d_in[18];
    const float* as_at1 = (const float*)d_in[19];
    const float* ad_at1 = (const float*)d_in[20];
    const float* b_at1 = (const float*)d_in[21];
    const float* w_ta1 = (const float*)d_in[22];
    const float* as_ta1 = (const float*)d_in[23];
    const float* ad_ta1 = (const float*)d_in[24];
    const float* b_ta1 = (const float*)d_in[25];
    const float* ln_g_tx = (const float*)d_in[26];
    const float* ln_b_tx = (const float*)d_in[27];
    const float* ln_g_addr = (const float*)d_in[28];
    const float* ln_b_addr = (const float*)d_in[29];
    const float* w_out = (const float*)d_in[30];
    const float* b_out = (const float*)d_in[31];
    float* out = (float*)d_out;

    float *p_htx64, *p_haddr64, *p_hs_at, *p_hd_at, *p_hs_ta, *p_hd_ta;
    float *p_agg_tx, *p_agg_addr, *p_htx, *p_haddr;
    float4 *p_als_at, *p_ald_at, *p_als_ta, *p_ald_ta, *p_al_at, *p_al_ta;
    int *p_cnt_tx, *p_cnt_addr, *p_rp_at, *p_rp_ta, *p_cur_tx, *p_cur_addr, *p_eidx_at, *p_eidx_ta;
    SYMADDR(p_htx64, g_htx64);     SYMADDR(p_haddr64, g_haddr64);
    SYMADDR(p_hs_at, g_hs_at);     SYMADDR(p_hd_at, g_hd_at);
    SYMADDR(p_hs_ta, g_hs_ta);     SYMADDR(p_hd_ta, g_hd_ta);
    SYMADDR(p_agg_tx, g_agg_tx);   SYMADDR(p_agg_addr, g_agg_addr);
    SYMADDR(p_htx, g_htx);         SYMADDR(p_haddr, g_haddr);
    SYMADDR(p_als_at, g_als_at);   SYMADDR(p_ald_at, g_ald_at);
    SYMADDR(p_als_ta, g_als_ta);   SYMADDR(p_ald_ta, g_ald_ta);
    SYMADDR(p_al_at, g_al_at);     SYMADDR(p_al_ta, g_al_ta);
    SYMADDR(p_cnt_tx, g_cnt_tx);   SYMADDR(p_cnt_addr, g_cnt_addr);
    SYMADDR(p_rp_at, g_rp_at);     SYMADDR(p_rp_ta, g_rp_ta);
    SYMADDR(p_cur_tx, g_cur_tx);   SYMADDR(p_cur_addr, g_cur_addr);
    SYMADDR(p_eidx_at, g_eidx_at); SYMADDR(p_eidx_ta, g_eidx_ta);

    const int TB = 256;
    // ---- CSR build (shared by both layers + pooling) ----
    hg_zero2<<<(N_ADDR + TB - 1) / TB, TB>>>(p_cnt_tx, N_TX, p_cnt_addr, N_ADDR);
    hg_count<<<(NE + TB - 1) / TB, TB>>>(tx_idx_at, p_cnt_tx, addr_idx_ta, p_cnt_addr);
    hg_exscan<<<1, 1024>>>(p_cnt_tx, p_rp_at, N_TX);
    hg_exscan<<<1, 1024>>>(p_cnt_addr, p_rp_ta, N_ADDR);
    cudaMemcpyAsync(p_cur_tx, p_rp_at, N_TX * sizeof(int), cudaMemcpyDeviceToDevice);
    cudaMemcpyAsync(p_cur_addr, p_rp_ta, N_ADDR * sizeof(int), cudaMemcpyDeviceToDevice);
    hg_fill<<<(NE + TB - 1) / TB, TB>>>(tx_idx_at, p_cur_tx, p_eidx_at,
                                        addr_idx_ta, p_cur_addr, p_eidx_ta);

    // ---- input projections ----
    launch_gemm(x_tx, w_in_tx, b_in_tx, p_htx64, N_TX, HDIM, F_TX);
    launch_gemm(x_addr, w_in_addr, b_in_addr, p_haddr64, N_ADDR, HDIM, F_ADDR);

    int cblk_tx = (N_TX * 32 + TB - 1) / TB;     // warp-per-node grids
    int cblk_addr = (N_ADDR * 32 + TB - 1) / TB;
    int eblk = (NE + TB - 1) / TB;

    for (int layer = 0; layer < 2; layer++) {
        const float* srcA_tx   = layer == 0 ? p_htx64 : p_htx;
        const float* srcA_addr = layer == 0 ? p_haddr64 : p_haddr;
        int K = layer == 0 ? HDIM : HD;
        const float* wa  = layer == 0 ? w_at0 : w_at1;
        const float* asa = layer == 0 ? as_at0 : as_at1;
        const float* ada = layer == 0 ? ad_at0 : ad_at1;
        const float* ba  = layer == 0 ? b_at0 : b_at1;
        const float* wt  = layer == 0 ? w_ta0 : w_ta1;
        const float* ast = layer == 0 ? as_ta0 : as_ta1;
        const float* adt = layer == 0 ? ad_ta0 : ad_ta1;
        const float* bt  = layer == 0 ? b_ta0 : b_ta1;

        // projections (hs: source-side, hd: dest-side; same W per relation)
        launch_gemm(srcA_addr, wa, nullptr, p_hs_at, N_ADDR, HD, K);
        launch_gemm(srcA_tx,   wa, nullptr, p_hd_at, N_TX,   HD, K);
        launch_gemm(srcA_tx,   wt, nullptr, p_hs_ta, N_TX,   HD, K);
        launch_gemm(srcA_addr, wt, nullptr, p_hd_ta, N_ADDR, HD, K);

        // node attention coefficients
        hg_node_coef<<<cblk_addr, TB>>>(p_hs_at, asa, p_als_at, N_ADDR);
        hg_node_coef<<<cblk_tx,   TB>>>(p_hd_at, ada, p_ald_at, N_TX);
        hg_node_coef<<<cblk_tx,   TB>>>(p_hs_ta, ast, p_als_ta, N_TX);
        hg_node_coef<<<cblk_addr, TB>>>(p_hd_ta, adt, p_ald_ta, N_ADDR);

        // per-edge logits
        hg_edge_al<<<eblk, TB>>>(addr_idx_at, tx_idx_at, p_als_at, p_ald_at, p_al_at);
        hg_edge_al<<<eblk, TB>>>(tx_idx_ta, addr_idx_ta, p_als_ta, p_ald_ta, p_al_ta);

        // segment softmax + aggregation
        hg_gat_agg<<<cblk_tx, TB>>>(p_hs_at, addr_idx_at, p_al_at, p_rp_at, p_eidx_at,
                                    p_agg_tx, N_TX);
        hg_gat_agg<<<cblk_addr, TB>>>(p_hs_ta, tx_idx_ta, p_al_ta, p_rp_ta, p_eidx_ta,
                                      p_agg_addr, N_ADDR);

        // bias + LN + (residual layer>=1) + ELU  -> new h (in-place into h buffers)
        hg_post_ln<<<N_TX, HD>>>(p_agg_tx, ba, ln_g_tx, ln_b_tx, p_htx, layer > 0 ? 1 : 0);
        hg_post_ln<<<N_ADDR, HD>>>(p_agg_addr, bt, ln_g_addr, ln_b_addr, p_haddr, layer > 0 ? 1 : 0);
    }

    // ---- scatter-mean pooling addr -> tx over 'at' edges ----
    hg_pool_mean<<<cblk_tx, TB>>>(p_haddr, addr_idx_at, p_rp_at, p_eidx_at, p_agg_tx, N_TX);

    // ---- output projection ----
    launch_gemm(p_agg_tx, w_out, b_out, out, N_TX, HD, HD);
}

// round 3
// speedup vs baseline: 1.9134x; 1.9134x over previous
#include <cuda_runtime.h>
#include <math.h>

// ---------------- problem constants ----------------
#define N_TX   100000
#define N_ADDR 200000
#define NE     400000
#define F_TX   165
#define F_ADDR 64
#define HDIM   64
#define HD     256
#define LN_EPS 1e-5f
#define NEG_SLOPE 0.2f

// ---------------- scratch (device globals; no cudaMalloc allowed) ----------------
__device__ float g_htx64[(size_t)N_TX * HDIM];
__device__ float g_haddr64[(size_t)N_ADDR * HDIM];
__device__ float g_hs_at[(size_t)N_ADDR * HD];   // addr projected by W_at (source side)
__device__ float g_hs_ta[(size_t)N_TX * HD];     // tx projected by W_ta (source side)
__device__ float g_agg_tx[(size_t)N_TX * HD];
__device__ float g_agg_addr[(size_t)N_ADDR * HD];
__device__ float g_htx[(size_t)N_TX * HD];
__device__ float g_haddr[(size_t)N_ADDR * HD];
__device__ float4 g_als_at[N_ADDR];
__device__ float4 g_ald_at[N_TX];
__device__ float4 g_als_ta[N_TX];
__device__ float4 g_ald_ta[N_ADDR];
__device__ float4 g_al_at[NE];
__device__ float4 g_al_ta[NE];
__device__ int g_cnt_tx[N_TX];
__device__ int g_cnt_addr[N_ADDR];
__device__ int g_rp_at[N_TX + 1];
__device__ int g_rp_ta[N_ADDR + 1];
__device__ int g_cur_tx[N_TX];
__device__ int g_cur_addr[N_ADDR];
__device__ int g_eidx_at[NE];
__device__ int g_eidx_ta[NE];
__device__ int g_bsum_tx[256];
__device__ int g_bsum_addr[256];
// folded attention weight vectors: Wv[k][head], K up to 256, 4 heads
__device__ float g_ws_at[HD * 4];
__device__ float g_wd_at[HD * 4];
__device__ float g_ws_ta[HD * 4];
__device__ float g_wd_ta[HD * 4];

// ---------------- SGEMM: C[M,N] = A[M,K] @ B[K,N] (+bias) ----------------
// 128x128 tile, BK=16, 256 threads, 8x8 per-thread, double-buffered smem
#define BM 128
#define BN 128
#define BK 16
#define TM 8
#define TN 8

__global__ __launch_bounds__(256)
void hg_sgemm(const float* __restrict__ A, const float* __restrict__ B,
              const float* __restrict__ bias, float* __restrict__ C,
              int M, int N, int K) {
    __shared__ float As[2][BK][BM];
    __shared__ float Bs[2][BK][BN];
    int tid = threadIdx.x;
    int row0 = blockIdx.y * BM, col0 = blockIdx.x * BN;
    int tx = tid & 15, ty = tid >> 4;
    int arow = tid >> 1, acol = (tid & 1) * 8;   // A: thread loads 8 k's of one row
    int brow = tid >> 4, bcol = (tid & 15) * 8;  // B: thread loads 8 n's of one k-row
    bool k4 = ((K & 3) == 0);
    int nk = (K + BK - 1) / BK;

    float ra[8];
    float4 rb0, rb1;

    float acc[TM][TN];
    #pragma unroll
    for (int i = 0; i < TM; i++)
        #pragma unroll
        for (int j = 0; j < TN; j++) acc[i][j] = 0.f;

    // ---- load helpers (into registers) ----
    auto loadA = [&](int k0) {
        int gr = row0 + arow;
        if (k4) {
            #pragma unroll
            for (int i = 0; i < 8; i += 4) {
                int gk = k0 + acol + i;
                float4 v = make_float4(0.f, 0.f, 0.f, 0.f);
                if (gr < M && gk < K) v = *(const float4*)(A + (long)gr * K + gk);
                ra[i] = v.x; ra[i + 1] = v.y; ra[i + 2] = v.z; ra[i + 3] = v.w;
            }
        } else {
            #pragma unroll
            for (int i = 0; i < 8; i++) {
                int gk = k0 + acol + i;
                ra[i] = (gr < M && gk < K) ? A[(long)gr * K + gk] : 0.f;
            }
        }
    };
    auto loadB = [&](int k0) {
        int gk = k0 + brow, gn = col0 + bcol;
        rb0 = make_float4(0.f, 0.f, 0.f, 0.f);
        rb1 = rb0;
        if (gk < K && gn < N) {  // N multiple of 8 -> gn<N implies gn+7<N
            rb0 = *(const float4*)(B + (long)gk * N + gn);
            rb1 = *(const float4*)(B + (long)gk * N + gn + 4);
        }
    };
    auto storeA = [&](int s) {
        #pragma unroll
        for (int i = 0; i < 8; i++) As[s][acol + i][arow] = ra[i];
    };
    auto storeB = [&](int s) {
        *(float4*)&Bs[s][brow][bcol] = rb0;
        *(float4*)&Bs[s][brow][bcol + 4] = rb1;
    };

    loadA(0); loadB(0);
    storeA(0); storeB(0);
    __syncthreads();

    int s = 0;
    for (int t = 0; t < nk; t++) {
        if (t + 1 < nk) { loadA((t + 1) * BK); loadB((t + 1) * BK); }
        #pragma unroll
        for (int k = 0; k < BK; k++) {
            float4 a0 = *(float4*)&As[s][k][ty * TM];
            float4 a1 = *(float4*)&As[s][k][ty * TM + 4];
            float4 b0 = *(float4*)&Bs[s][k][tx * TN];
            float4 b1 = *(float4*)&Bs[s][k][tx * TN + 4];
            float af[8] = {a0.x, a0.y, a0.z, a0.w, a1.x, a1.y, a1.z, a1.w};
            float bf[8] = {b0.x, b0.y, b0.z, b0.w, b1.x, b1.y, b1.z, b1.w};
            #pragma unroll
            for (int i = 0; i < TM; i++)
                #pragma unroll
                for (int j = 0; j < TN; j++) acc[i][j] += af[i] * bf[j];
        }
        if (t + 1 < nk) {
            storeA(s ^ 1); storeB(s ^ 1);
            __syncthreads();
            s ^= 1;
        }
    }

    int gc = col0 + tx * TN;
    if (gc >= N) return;   // N multiple of 8 -> full float4x2 valid when gc < N
    float bsv[8];
    #pragma unroll
    for (int j = 0; j < 8; j++) bsv[j] = bias ? bias[gc + j] : 0.f;
    #pragma unroll
    for (int i = 0; i < TM; i++) {
        int gr = row0 + ty * TM + i;
        if (gr >= M) continue;
        float* cp = C + (long)gr * N + gc;
        float4 v0 = make_float4(acc[i][0] + bsv[0], acc[i][1] + bsv[1],
                                acc[i][2] + bsv[2], acc[i][3] + bsv[3]);
        float4 v1 = make_float4(acc[i][4] + bsv[4], acc[i][5] + bsv[5],
                                acc[i][6] + bsv[6], acc[i][7] + bsv[7]);
        *(float4*)cp = v0;
        *(float4*)(cp + 4) = v1;
    }
}

// ---------------- CSR build ----------------
__global__ void hg_zero2(int* a, int na, int* b, int nb) {
    int i = blockIdx.x * blockDim.x + threadIdx.x;
    if (i < na) a[i] = 0;
    if (i < nb) b[i] = 0;
}

__global__ void hg_count(const int* __restrict__ dst_at, int* cnt_at,
                         const int* __restrict__ dst_ta, int* cnt_ta) {
    int i = blockIdx.x * blockDim.x + threadIdx.x;
    if (i < NE) {
        atomicAdd(&cnt_at[dst_at[i]], 1);
        atomicAdd(&cnt_ta[dst_ta[i]], 1);
    }
}

__device__ __forceinline__ int hg_warp_incl_scan(int v, int lane) {
    #pragma unroll
    for (int o = 1; o < 32; o <<= 1) {
        int t = __shfl_up_sync(0xffffffffu, v, o);
        if (lane >= o) v += t;
    }
    return v;
}

// per-1024 block inclusive scan; writes rp[i+1]=incl_scan (block-local); bsum[b] = block total
__global__ void hg_scan1(const int* __restrict__ cnt, int* __restrict__ rp,
                         int* __restrict__ bsum, int n) {
    __shared__ int ws[32];
    int lane = threadIdx.x & 31, wid = threadIdx.x >> 5;
    int i = blockIdx.x * 1024 + threadIdx.x;
    int v = (i < n) ? cnt[i] : 0;
    int s = hg_warp_incl_scan(v, lane);
    if (lane == 31) ws[wid] = s;
    __syncthreads();
    if (wid == 0) {
        int w = ws[lane];
        w = hg_warp_incl_scan(w, lane);
        ws[lane] = w;
    }
    __syncthreads();
    s += (wid ? ws[wid - 1] : 0);
    if (i < n) rp[i + 1] = s;
    if (bsum && threadIdx.x == 1023) bsum[blockIdx.x] = s;
}

// add scanned block sums
__global__ void hg_scan3(int* __restrict__ rp, const int* __restrict__ bsum, int n) {
    int i = blockIdx.x * blockDim.x + threadIdx.x;
    if (i == 0) rp[0] = 0;
    if (i < n) {
        int b = i >> 10;
        if (b > 0) rp[i + 1] += bsum[b - 1];
    }
}

__global__ void hg_fill(const int* __restrict__ dst_at, int* cur_at, int* eidx_at,
                        const int* __restrict__ dst_ta, int* cur_ta, int* eidx_ta) {
    int i = blockIdx.x * blockDim.x + threadIdx.x;
    if (i < NE) {
        int p = atomicAdd(&cur_at[dst_at[i]], 1);
        eidx_at[p] = i;
        int q = atomicAdd(&cur_ta[dst_ta[i]], 1);
        eidx_ta[q] = i;
    }
}

// ---------------- folded attention weights: Wv[k][head] = sum_c W[k][head*64+c]*a[head*64+c] ----------------
__global__ void hg_att_w(const float* __restrict__ W, const float* __restrict__ a,
                         float* __restrict__ Wv) {
    int k = blockIdx.x;
    int head = threadIdx.x >> 5, lane = threadIdx.x & 31;
    const float* wr = W + (long)k * HD + head * 64;
    const float* ar = a + head * 64;
    float s = wr[lane] * ar[lane] + wr[lane + 32] * ar[lane + 32];
    #pragma unroll
    for (int o = 16; o > 0; o >>= 1) s += __shfl_xor_sync(0xffffffffu, s, o);
    if (lane == 0) Wv[k * 4 + head] = s;
}

// ---------------- node coefficients directly from h: out[n] = h[n] @ Wv  (Kx4) ----------------
__global__ void hg_coef(const float* __restrict__ x, const float* __restrict__ Wv,
                        float4* __restrict__ out, int n, int K) {
    int warp = (blockIdx.x * blockDim.x + threadIdx.x) >> 5;
    int lane = threadIdx.x & 31;
    if (warp >= n) return;
    const float* xp = x + (long)warp * K;
    const float4* wv = (const float4*)Wv;
    float s0 = 0.f, s1 = 0.f, s2 = 0.f, s3 = 0.f;
    for (int k = lane; k < K; k += 32) {
        float xv = xp[k];
        float4 w = wv[k];
        s0 += xv * w.x; s1 += xv * w.y; s2 += xv * w.z; s3 += xv * w.w;
    }
    #pragma unroll
    for (int o = 16; o > 0; o >>= 1) {
        s0 += __shfl_xor_sync(0xffffffffu, s0, o);
        s1 += __shfl_xor_sync(0xffffffffu, s1, o);
        s2 += __shfl_xor_sync(0xffffffffu, s2, o);
        s3 += __shfl_xor_sync(0xffffffffu, s3, o);
    }
    if (lane == 0) out[warp] = make_float4(s0, s1, s2, s3);
}

// ---------------- per-edge attention logits (leaky relu) ----------------
__device__ __forceinline__ float hg_leaky(float v) { return v >= 0.f ? v : NEG_SLOPE * v; }

__global__ void hg_edge_al(const int* __restrict__ src, const int* __restrict__ dst,
                           const float4* __restrict__ als, const float4* __restrict__ ald,
                           float4* __restrict__ al) {
    int i = blockIdx.x * blockDim.x + threadIdx.x;
    if (i >= NE) return;
    float4 s = als[src[i]];
    float4 d = ald[dst[i]];
    float4 r;
    r.x = hg_leaky(s.x + d.x);
    r.y = hg_leaky(s.y + d.y);
    r.z = hg_leaky(s.z + d.z);
    r.w = hg_leaky(s.w + d.w);
    al[i] = r;
}

// ---------------- segment softmax + weighted aggregation (warp per dst node) ----------------
__global__ void hg_gat_agg(const float* __restrict__ hs, const int* __restrict__ src,
                           const float4* __restrict__ al, const int* __restrict__ rp,
                           const int* __restrict__ eidx, float* __restrict__ out, int ndst) {
    int warp = (blockIdx.x * blockDim.x + threadIdx.x) >> 5;
    int lane = threadIdx.x & 31;
    if (warp >= ndst) return;
    int beg = rp[warp], end = rp[warp + 1];
    int c0 = lane * 8;
    float* op = out + (long)warp * HD + c0;
    if (beg == end) {
        *(float4*)op = make_float4(0.f, 0.f, 0.f, 0.f);
        *(float4*)(op + 4) = make_float4(0.f, 0.f, 0.f, 0.f);
        return;
    }
    float m0 = -3.4e38f, m1 = -3.4e38f, m2 = -3.4e38f, m3 = -3.4e38f;
    for (int t = beg; t < end; t++) {
        float4 a = al[eidx[t]];
        m0 = fmaxf(m0, a.x); m1 = fmaxf(m1, a.y);
        m2 = fmaxf(m2, a.z); m3 = fmaxf(m3, a.w);
    }
    float d0 = 0.f, d1 = 0.f, d2 = 0.f, d3 = 0.f;
    for (int t = beg; t < end; t++) {
        float4 a = al[eidx[t]];
        d0 += __expf(a.x - m0); d1 += __expf(a.y - m1);
        d2 += __expf(a.z - m2); d3 += __expf(a.w - m3);
    }
    int hl = lane >> 3;  // 8 consecutive channels -> one head
    float mh = (hl & 2) ? ((hl & 1) ? m3 : m2) : ((hl & 1) ? m1 : m0);
    float dh = (hl & 2) ? ((hl & 1) ? d3 : d2) : ((hl & 1) ? d1 : d0);
    float inv = 1.f / dh;
    float acc[8] = {0.f, 0.f, 0.f, 0.f, 0.f, 0.f, 0.f, 0.f};
    for (int t = beg; t < end; t++) {
        int eid = eidx[t];
        int sidx = src[eid];
        float4 a = al[eid];
        float av = (hl & 2) ? ((hl & 1) ? a.w : a.z) : ((hl & 1) ? a.y : a.x);
        float alpha = __expf(av - mh) * inv;
        const float4* hp = (const float4*)(hs + (long)sidx * HD + c0);
        float4 v0 = hp[0], v1 = hp[1];
        acc[0] += alpha * v0.x; acc[1] += alpha * v0.y;
        acc[2] += alpha * v0.z; acc[3] += alpha * v0.w;
        acc[4] += alpha * v1.x; acc[5] += alpha * v1.y;
        acc[6] += alpha * v1.z; acc[7] += alpha * v1.w;
    }
    *(float4*)op = make_float4(acc[0], acc[1], acc[2], acc[3]);
    *(float4*)(op + 4) = make_float4(acc[4], acc[5], acc[6], acc[7]);
}

// ---------------- bias + LayerNorm + (residual) + ELU, warp per row ----------------
__global__ void hg_post_ln(const float* __restrict__ agg, const float* __restrict__ bias,
                           const float* __restrict__ gam, const float* __restrict__ bet,
                           float* __restrict__ h, int residual, int nrows) {
    int warp = (blockIdx.x * blockDim.x + threadIdx.x) >> 5;
    int lane = threadIdx.x & 31;
    if (warp >= nrows) return;
    int c0 = lane * 8;
    const float4* ap = (const float4*)(agg + (long)warp * HD + c0);
    const float4* bp = (const float4*)(bias + c0);
    float4 a0 = ap[0], a1 = ap[1];
    float4 b0 = bp[0], b1 = bp[1];
    float v[8] = {a0.x + b0.x, a0.y + b0.y, a0.z + b0.z, a0.w + b0.w,
                  a1.x + b1.x, a1.y + b1.y, a1.z + b1.z, a1.w + b1.w};
    float sum = 0.f, sq = 0.f;
    #pragma unroll
    for (int j = 0; j < 8; j++) { sum += v[j]; sq += v[j] * v[j]; }
    #pragma unroll
    for (int o = 16; o > 0; o >>= 1) {
        sum += __shfl_xor_sync(0xffffffffu, sum, o);
        sq  += __shfl_xor_sync(0xffffffffu, sq, o);
    }
    float mu = sum * (1.f / HD);
    float var = sq * (1.f / HD) - mu * mu;
    float rstd = rsqrtf(var + LN_EPS);
    const float4* gp = (const float4*)(gam + c0);
    const float4* ep = (const float4*)(bet + c0);
    float4 g0 = gp[0], g1 = gp[1];
    float4 e0 = ep[0], e1 = ep[1];
    float gm[8] = {g0.x, g0.y, g0.z, g0.w, g1.x, g1.y, g1.z, g1.w};
    float bt[8] = {e0.x, e0.y, e0.z, e0.w, e1.x, e1.y, e1.z, e1.w};
    float* hp = h + (long)warp * HD + c0;
    float r[8] = {0.f, 0.f, 0.f, 0.f, 0.f, 0.f, 0.f, 0.f};
    if (residual) {
        float4 r0 = ((const float4*)hp)[0], r1 = ((const float4*)hp)[1];
        r[0] = r0.x; r[1] = r0.y; r[2] = r0.z; r[3] = r0.w;
        r[4] = r1.x; r[5] = r1.y; r[6] = r1.z; r[7] = r1.w;
    }
    float y[8];
    #pragma unroll
    for (int j = 0; j < 8; j++) {
        float t = (v[j] - mu) * rstd * gm[j] + bt[j] + r[j];
        y[j] = t > 0.f ? t : expm1f(t);
    }
    *(float4*)hp = make_float4(y[0], y[1], y[2], y[3]);
    *(float4*)(hp + 4) = make_float4(y[4], y[5], y[6], y[7]);
}

// ---------------- mean pooling addr -> tx (warp per tx node) ----------------
__global__ void hg_pool_mean(const float* __restrict__ haddr, const int* __restrict__ src,
                             const int* __restrict__ rp, const int* __restrict__ eidx,
                             float* __restrict__ out, int ndst) {
    int warp = (blockIdx.x * blockDim.x + threadIdx.x) >> 5;
    int lane = threadIdx.x & 31;
    if (warp >= ndst) return;
    int beg = rp[warp], end = rp[warp + 1];
    int c0 = lane * 8;
    float acc[8] = {0.f, 0.f, 0.f, 0.f, 0.f, 0.f, 0.f, 0.f};
    for (int t = beg; t < end; t++) {
        int s = src[eidx[t]];
        const float4* hp = (const float4*)(haddr + (long)s * HD + c0);
        float4 v0 = hp[0], v1 = hp[1];
        acc[0] += v0.x; acc[1] += v0.y; acc[2] += v0.z; acc[3] += v0.w;
        acc[4] += v1.x; acc[5] += v1.y; acc[6] += v1.z; acc[7] += v1.w;
    }
    int deg = end - beg;
    float inv = 1.f / (float)(deg > 0 ? deg : 1);
    float* op = out + (long)warp * HD + c0;
    *(float4*)op = make_float4(acc[0] * inv, acc[1] * inv, acc[2] * inv, acc[3] * inv);
    *(float4*)(op + 4) = make_float4(acc[4] * inv, acc[5] * inv, acc[6] * inv, acc[7] * inv);
}

// ---------------- host launcher ----------------
#define SYMADDR(p, s) do { void* _t = nullptr; cudaGetSymbolAddress(&_t, s); p = (decltype(p))_t; } while (0)

static inline void launch_gemm(const float* A, const float* B, const float* bias,
                               float* C, int M, int N, int K) {
    dim3 grid((N + BN - 1) / BN, (M + BM - 1) / BM);
    hg_sgemm<<<grid, 256>>>(A, B, bias, C, M, N, K);
}

extern "C" void kernel_launch(void* const* d_in, const int* in_sizes, int n_in,
                              void* d_out, int out_size) {
    const float* x_tx      = (const float*)d_in[0];
    const float* x_addr    = (const float*)d_in[1];
    const int*   addr_idx_at = (const int*)d_in[2];
    const int*   tx_idx_at   = (const int*)d_in[3];
    const int*   tx_idx_ta   = (const int*)d_in[4];
    const int*   addr_idx_ta = (const int*)d_in[5];
    const float* w_in_tx   = (const float*)d_in[6];
    const float* b_in_tx   = (const float*)d_in[7];
    const float* w_in_addr = (const float*)d_in[8];
    const float* b_in_addr = (const float*)d_in[9];
    const float* w_at0 = (const float*)d_in[10];
    const float* as_at0 = (const float*)d_in[11];
    const float* ad_at0 = (const float*)d_in[12];
    const float* b_at0 = (const float*)d_in[13];
    const float* w_ta0 = (const float*)d_in[14];
    const float* as_ta0 = (const float*)d_in[15];
    const float* ad_ta0 = (const float*)d_in[16];
    const float* b_ta0 = (const float*)d_in[17];
    const float* w_at1 = (const float*)d_in[18];
    const float* as_at1 = (const float*)d_in[19];
    const float* ad_at1 = (const float*)d_in[20];
    const float* b_at1 = (const float*)d_in[21];
    const float* w_ta1 = (const float*)d_in[22];
    const float* as_ta1 = (const float*)d_in[23];
    const float* ad_ta1 = (const float*)d_in[24];
    const float* b_ta1 = (const float*)d_in[25];
    const float* ln_g_tx = (const float*)d_in[26];
    const float* ln_b_tx = (const float*)d_in[27];
    const float* ln_g_addr = (const float*)d_in[28];
    const float* ln_b_addr = (const float*)d_in[29];
    const float* w_out = (const float*)d_in[30];
    const float* b_out = (const float*)d_in[31];
    float* out = (float*)d_out;

    float *p_htx64, *p_haddr64, *p_hs_at, *p_hs_ta;
    float *p_agg_tx, *p_agg_addr, *p_htx, *p_haddr;
    float4 *p_als_at, *p_ald_at, *p_als_ta, *p_ald_ta, *p_al_at, *p_al_ta;
    int *p_cnt_tx, *p_cnt_addr, *p_rp_at, *p_rp_ta, *p_cur_tx, *p_cur_addr;
    int *p_eidx_at, *p_eidx_ta, *p_bsum_tx, *p_bsum_addr;
    float *p_ws_at, *p_wd_at, *p_ws_ta, *p_wd_ta;
    SYMADDR(p_htx64, g_htx64);     SYMADDR(p_haddr64, g_haddr64);
    SYMADDR(p_hs_at, g_hs_at);     SYMADDR(p_hs_ta, g_hs_ta);
    SYMADDR(p_agg_tx, g_agg_tx);   SYMADDR(p_agg_addr, g_agg_addr);
    SYMADDR(p_htx, g_htx);         SYMADDR(p_haddr, g_haddr);
    SYMADDR(p_als_at, g_als_at);   SYMADDR(p_ald_at, g_ald_at);
    SYMADDR(p_als_ta, g_als_ta);   SYMADDR(p_ald_ta, g_ald_ta);
    SYMADDR(p_al_at, g_al_at);     SYMADDR(p_al_ta, g_al_ta);
    SYMADDR(p_cnt_tx, g_cnt_tx);   SYMADDR(p_cnt_addr, g_cnt_addr);
    SYMADDR(p_rp_at, g_rp_at);     SYMADDR(p_rp_ta, g_rp_ta);
    SYMADDR(p_cur_tx, g_cur_tx);   SYMADDR(p_cur_addr, g_cur_addr);
    SYMADDR(p_eidx_at, g_eidx_at); SYMADDR(p_eidx_ta, g_eidx_ta);
    SYMADDR(p_bsum_tx, g_bsum_tx); SYMADDR(p_bsum_addr, g_bsum_addr);
    SYMADDR(p_ws_at, g_ws_at);     SYMADDR(p_wd_at, g_wd_at);
    SYMADDR(p_ws_ta, g_ws_ta);     SYMADDR(p_wd_ta, g_wd_ta);

    const int TB = 256;
    const int nb_tx = (N_TX + 1023) / 1024;      // 98
    const int nb_addr = (N_ADDR + 1023) / 1024;  // 196

    // ---- CSR build (shared by both layers + pooling) ----
    hg_zero2<<<(N_ADDR + TB - 1) / TB, TB>>>(p_cnt_tx, N_TX, p_cnt_addr, N_ADDR);
    hg_count<<<(NE + TB - 1) / TB, TB>>>(tx_idx_at, p_cnt_tx, addr_idx_ta, p_cnt_addr);
    // multi-block exclusive scan: per-block scan -> scan block sums (in place) -> add
    hg_scan1<<<nb_tx, 1024>>>(p_cnt_tx, p_rp_at, p_bsum_tx, N_TX);
    hg_scan1<<<nb_addr, 1024>>>(p_cnt_addr, p_rp_ta, p_bsum_addr, N_ADDR);
    hg_scan1<<<1, 1024>>>(p_bsum_tx, p_bsum_tx - 1, nullptr, nb_tx);       // in-place inclusive
    hg_scan1<<<1, 1024>>>(p_bsum_addr, p_bsum_addr - 1, nullptr, nb_addr);
    hg_scan3<<<(N_TX + TB - 1) / TB, TB>>>(p_rp_at, p_bsum_tx, N_TX);
    hg_scan3<<<(N_ADDR + TB - 1) / TB, TB>>>(p_rp_ta, p_bsum_addr, N_ADDR);
    cudaMemcpyAsync(p_cur_tx, p_rp_at, N_TX * sizeof(int), cudaMemcpyDeviceToDevice);
    cudaMemcpyAsync(p_cur_addr, p_rp_ta, N_ADDR * sizeof(int), cudaMemcpyDeviceToDevice);
    hg_fill<<<(NE + TB - 1) / TB, TB>>>(tx_idx_at, p_cur_tx, p_eidx_at,
                                        addr_idx_ta, p_cur_addr, p_eidx_ta);

    // ---- input projections ----
    launch_gemm(x_tx, w_in_tx, b_in_tx, p_htx64, N_TX, HDIM, F_TX);
    launch_gemm(x_addr, w_in_addr, b_in_addr, p_haddr64, N_ADDR, HDIM, F_ADDR);

    int cblk_tx = (N_TX * 32 + TB - 1) / TB;     // warp-per-node grids
    int cblk_addr = (N_ADDR * 32 + TB - 1) / TB;
    int eblk = (NE + TB - 1) / TB;

    for (int layer = 0; layer < 2; layer++) {
        const float* srcA_tx   = layer == 0 ? p_htx64 : p_htx;
        const float* srcA_addr = layer == 0 ? p_haddr64 : p_haddr;
        int K = layer == 0 ? HDIM : HD;
        const float* wa  = layer == 0 ? w_at0 : w_at1;
        const float* asa = layer == 0 ? as_at0 : as_at1;
        const float* ada = layer == 0 ? ad_at0 : ad_at1;
        const float* ba  = layer == 0 ? b_at0 : b_at1;
        const float* wt  = layer == 0 ? w_ta0 : w_ta1;
        const float* ast = layer == 0 ? as_ta0 : as_ta1;
        const float* adt = layer == 0 ? ad_ta0 : ad_ta1;
        const float* bt  = layer == 0 ? b_ta0 : b_ta1;

        // fold attention vectors into W:  Wv[k][h] = sum_c W[k][h*64+c]*a[h][c]
        hg_att_w<<<K, 128>>>(wa, asa, p_ws_at);
        hg_att_w<<<K, 128>>>(wa, ada, p_wd_at);
        hg_att_w<<<K, 128>>>(wt, ast, p_ws_ta);
        hg_att_w<<<K, 128>>>(wt, adt, p_wd_ta);

        // source-side full projections (needed for aggregation)
        launch_gemm(srcA_addr, wa, nullptr, p_hs_at, N_ADDR, HD, K);
        launch_gemm(srcA_tx,   wt, nullptr, p_hs_ta, N_TX,   HD, K);

        // attention node coefficients directly from h (dest-side GEMMs eliminated)
        hg_coef<<<cblk_addr, TB>>>(srcA_addr, p_ws_at, p_als_at, N_ADDR, K);
        hg_coef<<<cblk_tx,   TB>>>(srcA_tx,   p_wd_at, p_ald_at, N_TX,   K);
        hg_coef<<<cblk_tx,   TB>>>(srcA_tx,   p_ws_ta, p_als_ta, N_TX,   K);
        hg_coef<<<cblk_addr, TB>>>(srcA_addr, p_wd_ta, p_ald_ta, N_ADDR, K);

        // per-edge logits
        hg_edge_al<<<eblk, TB>>>(addr_idx_at, tx_idx_at, p_als_at, p_ald_at, p_al_at);
        hg_edge_al<<<eblk, TB>>>(tx_idx_ta, addr_idx_ta, p_als_ta, p_ald_ta, p_al_ta);

        // segment softmax + aggregation
        hg_gat_agg<<<cblk_tx, TB>>>(p_hs_at, addr_idx_at, p_al_at, p_rp_at, p_eidx_at,
                                    p_agg_tx, N_TX);
        hg_gat_agg<<<cblk_addr, TB>>>(p_hs_ta, tx_idx_ta, p_al_ta, p_rp_ta, p_eidx_ta,
                                      p_agg_addr, N_ADDR);

        // bias + LN + (residual layer>=1) + ELU -> new h
        hg_post_ln<<<cblk_tx, TB>>>(p_agg_tx, ba, ln_g_tx, ln_b_tx, p_htx,
                                    layer > 0 ? 1 : 0, N_TX);
        hg_post_ln<<<cblk_addr, TB>>>(p_agg_addr, bt, ln_g_addr, ln_b_addr, p_haddr,
                                      layer > 0 ? 1 : 0, N_ADDR);
    }

    // ---- scatter-mean pooling addr -> tx over 'at' edges ----
    hg_pool_mean<<<cblk_tx, TB>>>(p_haddr, addr_idx_at, p_rp_at, p_eidx_at, p_agg_tx, N_TX);

    // ---- output projection ----
    launch_gemm(p_agg_tx, w_out, b_out, out, N_TX, HD, HD);
}

// round 4
// speedup vs baseline: 2.0966x; 1.0957x over previous
#include <cuda_runtime.h>
#include <math.h>

// ---------------- problem constants ----------------
#define N_TX   100000
#define N_ADDR 200000
#define NE     400000
#define F_TX   165
#define F_ADDR 64
#define HDIM   64
#define HD     256
#define LN_EPS 1e-5f
#define NEG_SLOPE 0.2f

// ---------------- scratch (device globals; no cudaMalloc allowed) ----------------
__device__ float g_htx64[(size_t)N_TX * HDIM];
__device__ float g_haddr64[(size_t)N_ADDR * HDIM];
__device__ float g_hs_at[(size_t)N_ADDR * HD];   // addr projected by W_at (source side)
__device__ float g_hs_ta[(size_t)N_TX * HD];     // tx projected by W_ta (source side)
__device__ float g_agg_tx[(size_t)N_TX * HD];
__device__ float g_agg_addr[(size_t)N_ADDR * HD];
__device__ float g_htx[(size_t)N_TX * HD];
__device__ float g_haddr[(size_t)N_ADDR * HD];
__device__ float4 g_als_at[N_ADDR];
__device__ float4 g_ald_at[N_TX];
__device__ float4 g_als_ta[N_TX];
__device__ float4 g_ald_ta[N_ADDR];
__device__ float4 g_al_at[NE];
__device__ float4 g_al_ta[NE];
__device__ int g_cnt_tx[N_TX];
__device__ int g_cnt_addr[N_ADDR];
__device__ int g_rp_at[N_TX + 1];
__device__ int g_rp_ta[N_ADDR + 1];
__device__ int g_cur_tx[N_TX];
__device__ int g_cur_addr[N_ADDR];
__device__ int g_eidx_at[NE];
__device__ int g_eidx_ta[NE];
__device__ int g_bsum_tx[256];
__device__ int g_bsum_addr[256];
// folded attention weight vectors: Wv[k][head], K up to 256, 4 heads
__device__ float g_ws_at[HD * 4];
__device__ float g_wd_at[HD * 4];
__device__ float g_ws_ta[HD * 4];
__device__ float g_wd_ta[HD * 4];

// ---------------- packed f32x2 helpers (sm_103a FFMA2 pipe) ----------------
__device__ __forceinline__ unsigned long long hg_pack2(float x, float y) {
    unsigned long long r;
    asm("mov.b64 %0, {%1, %2};" : "=l"(r) : "f"(x), "f"(y));
    return r;
}
__device__ __forceinline__ void hg_unpack2(unsigned long long v, float& x, float& y) {
    asm("mov.b64 {%0, %1}, %2;" : "=f"(x), "=f"(y) : "l"(v));
}
__device__ __forceinline__ void hg_ffma2(unsigned long long& d,
                                         unsigned long long a, unsigned long long b) {
    asm("fma.rn.f32x2 %0, %1, %2, %0;" : "+l"(d) : "l"(a), "l"(b));
}

// ---------------- SGEMM: C[M,N] = A[M,K] @ B[K,N] (+bias) ----------------
// 128x128 tile, BK=16, 256 threads, 8x8 per-thread, double-buffered smem,
// inner loop on packed fma.rn.f32x2 (2 fp32 FMA per instruction).
#define BM 128
#define BN 128
#define BK 16
#define TM 8
#define TN 8

__global__ __launch_bounds__(256)
void hg_sgemm(const float* __restrict__ A, const float* __restrict__ B,
              const float* __restrict__ bias, float* __restrict__ C,
              int M, int N, int K) {
    __shared__ float As[2][BK][BM];
    __shared__ float Bs[2][BK][BN];
    int tid = threadIdx.x;
    int row0 = blockIdx.y * BM, col0 = blockIdx.x * BN;
    int tx = tid & 15, ty = tid >> 4;
    int arow = tid >> 1, acol = (tid & 1) * 8;   // A: thread loads 8 k's of one row
    int brow = tid >> 4, bcol = (tid & 15) * 8;  // B: thread loads 8 n's of one k-row
    bool k4 = ((K & 3) == 0);
    int nk = (K + BK - 1) / BK;

    float ra[8];
    float4 rb0, rb1;

    unsigned long long acc2[TM][TN / 2];
    #pragma unroll
    for (int i = 0; i < TM; i++)
        #pragma unroll
        for (int j = 0; j < TN / 2; j++) acc2[i][j] = 0ull;  // {0.f, 0.f}

    auto loadA = [&](int k0) {
        int gr = row0 + arow;
        if (k4) {
            #pragma unroll
            for (int i = 0; i < 8; i += 4) {
                int gk = k0 + acol + i;
                float4 v = make_float4(0.f, 0.f, 0.f, 0.f);
                if (gr < M && gk < K) v = *(const float4*)(A + (long)gr * K + gk);
                ra[i] = v.x; ra[i + 1] = v.y; ra[i + 2] = v.z; ra[i + 3] = v.w;
            }
        } else {
            #pragma unroll
            for (int i = 0; i < 8; i++) {
                int gk = k0 + acol + i;
                ra[i] = (gr < M && gk < K) ? A[(long)gr * K + gk] : 0.f;
            }
        }
    };
    auto loadB = [&](int k0) {
        int gk = k0 + brow, gn = col0 + bcol;
        rb0 = make_float4(0.f, 0.f, 0.f, 0.f);
        rb1 = rb0;
        if (gk < K && gn < N) {  // N multiple of 8 -> gn<N implies gn+7<N
            rb0 = *(const float4*)(B + (long)gk * N + gn);
            rb1 = *(const float4*)(B + (long)gk * N + gn + 4);
        }
    };
    auto storeA = [&](int s) {
        #pragma unroll
        for (int i = 0; i < 8; i++) As[s][acol + i][arow] = ra[i];
    };
    auto storeB = [&](int s) {
        *(float4*)&Bs[s][brow][bcol] = rb0;
        *(float4*)&Bs[s][brow][bcol + 4] = rb1;
    };

    loadA(0); loadB(0);
    storeA(0); storeB(0);
    __syncthreads();

    int s = 0;
    for (int t = 0; t < nk; t++) {
        if (t + 1 < nk) { loadA((t + 1) * BK); loadB((t + 1) * BK); }
        #pragma unroll
        for (int k = 0; k < BK; k++) {
            float4 a0 = *(float4*)&As[s][k][ty * TM];
            float4 a1 = *(float4*)&As[s][k][ty * TM + 4];
            float4 b0 = *(float4*)&Bs[s][k][tx * TN];
            float4 b1 = *(float4*)&Bs[s][k][tx * TN + 4];
            unsigned long long b2[4];
            b2[0] = hg_pack2(b0.x, b0.y);
            b2[1] = hg_pack2(b0.z, b0.w);
            b2[2] = hg_pack2(b1.x, b1.y);
            b2[3] = hg_pack2(b1.z, b1.w);
            float af[8] = {a0.x, a0.y, a0.z, a0.w, a1.x, a1.y, a1.z, a1.w};
            #pragma unroll
            for (int i = 0; i < TM; i++) {
                unsigned long long a2 = hg_pack2(af[i], af[i]);
                #pragma unroll
                for (int j = 0; j < TN / 2; j++) hg_ffma2(acc2[i][j], a2, b2[j]);
            }
        }
        if (t + 1 < nk) {
            storeA(s ^ 1); storeB(s ^ 1);
            __syncthreads();
            s ^= 1;
        }
    }

    int gc = col0 + tx * TN;
    if (gc >= N) return;   // N multiple of 8 -> full float4x2 valid when gc < N
    float bsv[8];
    #pragma unroll
    for (int j = 0; j < 8; j++) bsv[j] = bias ? bias[gc + j] : 0.f;
    #pragma unroll
    for (int i = 0; i < TM; i++) {
        int gr = row0 + ty * TM + i;
        if (gr >= M) continue;
        float acc[8];
        #pragma unroll
        for (int j = 0; j < 4; j++) hg_unpack2(acc2[i][j], acc[2 * j], acc[2 * j + 1]);
        float* cp = C + (long)gr * N + gc;
        float4 v0 = make_float4(acc[0] + bsv[0], acc[1] + bsv[1],
                                acc[2] + bsv[2], acc[3] + bsv[3]);
        float4 v1 = make_float4(acc[4] + bsv[4], acc[5] + bsv[5],
                                acc[6] + bsv[6], acc[7] + bsv[7]);
        *(float4*)cp = v0;
        *(float4*)(cp + 4) = v1;
    }
}

// ---------------- CSR build ----------------
__global__ void hg_zero2(int* a, int na, int* b, int nb) {
    int i = blockIdx.x * blockDim.x + threadIdx.x;
    if (i < na) a[i] = 0;
    if (i < nb) b[i] = 0;
}

__global__ void hg_count(const int* __restrict__ dst_at, int* cnt_at,
                         const int* __restrict__ dst_ta, int* cnt_ta) {
    int i = blockIdx.x * blockDim.x + threadIdx.x;
    if (i < NE) {
        atomicAdd(&cnt_at[dst_at[i]], 1);
        atomicAdd(&cnt_ta[dst_ta[i]], 1);
    }
}

__device__ __forceinline__ int hg_warp_incl_scan(int v, int lane) {
    #pragma unroll
    for (int o = 1; o < 32; o <<= 1) {
        int t = __shfl_up_sync(0xffffffffu, v, o);
        if (lane >= o) v += t;
    }
    return v;
}

// per-1024 block inclusive scan; writes rp[i+1]=incl_scan (block-local); bsum[b] = block total
__global__ void hg_scan1(const int* __restrict__ cnt, int* __restrict__ rp,
                         int* __restrict__ bsum, int n) {
    __shared__ int ws[32];
    int lane = threadIdx.x & 31, wid = threadIdx.x >> 5;
    int i = blockIdx.x * 1024 + threadIdx.x;
    int v = (i < n) ? cnt[i] : 0;
    int s = hg_warp_incl_scan(v, lane);
    if (lane == 31) ws[wid] = s;
    __syncthreads();
    if (wid == 0) {
        int w = ws[lane];
        w = hg_warp_incl_scan(w, lane);
        ws[lane] = w;
    }
    __syncthreads();
    s += (wid ? ws[wid - 1] : 0);
    if (i < n) rp[i + 1] = s;
    if (bsum && threadIdx.x == 1023) bsum[blockIdx.x] = s;
}

// add scanned block sums
__global__ void hg_scan3(int* __restrict__ rp, const int* __restrict__ bsum, int n) {
    int i = blockIdx.x * blockDim.x + threadIdx.x;
    if (i == 0) rp[0] = 0;
    if (i < n) {
        int b = i >> 10;
        if (b > 0) rp[i + 1] += bsum[b - 1];
    }
}

__global__ void hg_fill(const int* __restrict__ dst_at, int* cur_at, int* eidx_at,
                        const int* __restrict__ dst_ta, int* cur_ta, int* eidx_ta) {
    int i = blockIdx.x * blockDim.x + threadIdx.x;
    if (i < NE) {
        int p = atomicAdd(&cur_at[dst_at[i]], 1);
        eidx_at[p] = i;
        int q = atomicAdd(&cur_ta[dst_ta[i]], 1);
        eidx_ta[q] = i;
    }
}

// ---------------- folded attention weights: Wv[k][head] = sum_c W[k][head*64+c]*a[head*64+c] ----------------
__global__ void hg_att_w(const float* __restrict__ W, const float* __restrict__ a,
                         float* __restrict__ Wv) {
    int k = blockIdx.x;
    int head = threadIdx.x >> 5, lane = threadIdx.x & 31;
    const float* wr = W + (long)k * HD + head * 64;
    const float* ar = a + head * 64;
    float s = wr[lane] * ar[lane] + wr[lane + 32] * ar[lane + 32];
    #pragma unroll
    for (int o = 16; o > 0; o >>= 1) s += __shfl_xor_sync(0xffffffffu, s, o);
    if (lane == 0) Wv[k * 4 + head] = s;
}

// ---------------- fused node coefficients: out1[n] = x[n]@Wv1, out2[n] = x[n]@Wv2 ----------------
__global__ void hg_coef2(const float* __restrict__ x,
                         const float* __restrict__ Wv1, const float* __restrict__ Wv2,
                         float4* __restrict__ out1, float4* __restrict__ out2,
                         int n, int K) {
    int warp = (blockIdx.x * blockDim.x + threadIdx.x) >> 5;
    int lane = threadIdx.x & 31;
    if (warp >= n) return;
    const float* xp = x + (long)warp * K;
    const float4* wv1 = (const float4*)Wv1;
    const float4* wv2 = (const float4*)Wv2;
    float s0 = 0.f, s1 = 0.f, s2 = 0.f, s3 = 0.f;
    float t0 = 0.f, t1 = 0.f, t2 = 0.f, t3 = 0.f;
    for (int k = lane; k < K; k += 32) {
        float xv = xp[k];
        float4 w1 = wv1[k];
        float4 w2 = wv2[k];
        s0 += xv * w1.x; s1 += xv * w1.y; s2 += xv * w1.z; s3 += xv * w1.w;
        t0 += xv * w2.x; t1 += xv * w2.y; t2 += xv * w2.z; t3 += xv * w2.w;
    }
    #pragma unroll
    for (int o = 16; o > 0; o >>= 1) {
        s0 += __shfl_xor_sync(0xffffffffu, s0, o);
        s1 += __shfl_xor_sync(0xffffffffu, s1, o);
        s2 += __shfl_xor_sync(0xffffffffu, s2, o);
        s3 += __shfl_xor_sync(0xffffffffu, s3, o);
        t0 += __shfl_xor_sync(0xffffffffu, t0, o);
        t1 += __shfl_xor_sync(0xffffffffu, t1, o);
        t2 += __shfl_xor_sync(0xffffffffu, t2, o);
        t3 += __shfl_xor_sync(0xffffffffu, t3, o);
    }
    if (lane == 0) {
        out1[warp] = make_float4(s0, s1, s2, s3);
        out2[warp] = make_float4(t0, t1, t2, t3);
    }
}

// ---------------- per-edge attention logits (leaky relu) ----------------
__device__ __forceinline__ float hg_leaky(float v) { return v >= 0.f ? v : NEG_SLOPE * v; }

__global__ void hg_edge_al(const int* __restrict__ src, const int* __restrict__ dst,
                           const float4* __restrict__ als, const float4* __restrict__ ald,
                           float4* __restrict__ al) {
    int i = blockIdx.x * blockDim.x + threadIdx.x;
    if (i >= NE) return;
    float4 s = als[src[i]];
    float4 d = ald[dst[i]];
    float4 r;
    r.x = hg_leaky(s.x + d.x);
    r.y = hg_leaky(s.y + d.y);
    r.z = hg_leaky(s.z + d.z);
    r.w = hg_leaky(s.w + d.w);
    al[i] = r;
}

// ---------------- segment softmax + weighted aggregation (warp per dst node) ----------------
__global__ void hg_gat_agg(const float* __restrict__ hs, const int* __restrict__ src,
                           const float4* __restrict__ al, const int* __restrict__ rp,
                           const int* __restrict__ eidx, float* __restrict__ out, int ndst) {
    int warp = (blockIdx.x * blockDim.x + threadIdx.x) >> 5;
    int lane = threadIdx.x & 31;
    if (warp >= ndst) return;
    int beg = rp[warp], end = rp[warp + 1];
    int c0 = lane * 8;
    float* op = out + (long)warp * HD + c0;
    if (beg == end) {
        *(float4*)op = make_float4(0.f, 0.f, 0.f, 0.f);
        *(float4*)(op + 4) = make_float4(0.f, 0.f, 0.f, 0.f);
        return;
    }
    float m0 = -3.4e38f, m1 = -3.4e38f, m2 = -3.4e38f, m3 = -3.4e38f;
    for (int t = beg; t < end; t++) {
        float4 a = al[eidx[t]];
        m0 = fmaxf(m0, a.x); m1 = fmaxf(m1, a.y);
        m2 = fmaxf(m2, a.z); m3 = fmaxf(m3, a.w);
    }
    float d0 = 0.f, d1 = 0.f, d2 = 0.f, d3 = 0.f;
    for (int t = beg; t < end; t++) {
        float4 a = al[eidx[t]];
        d0 += __expf(a.x - m0); d1 += __expf(a.y - m1);
        d2 += __expf(a.z - m2); d3 += __expf(a.w - m3);
    }
    int hl = lane >> 3;  // 8 consecutive channels -> one head
    float mh = (hl & 2) ? ((hl & 1) ? m3 : m2) : ((hl & 1) ? m1 : m0);
    float dh = (hl & 2) ? ((hl & 1) ? d3 : d2) : ((hl & 1) ? d1 : d0);
    float inv = 1.f / dh;
    float acc[8] = {0.f, 0.f, 0.f, 0.f, 0.f, 0.f, 0.f, 0.f};
    for (int t = beg; t < end; t++) {
        int eid = eidx[t];
        int sidx = src[eid];
        float4 a = al[eid];
        float av = (hl & 2) ? ((hl & 1) ? a.w : a.z) : ((hl & 1) ? a.y : a.x);
        float alpha = __expf(av - mh) * inv;
        const float4* hp = (const float4*)(hs + (long)sidx * HD + c0);
        float4 v0 = hp[0], v1 = hp[1];
        acc[0] += alpha * v0.x; acc[1] += alpha * v0.y;
        acc[2] += alpha * v0.z; acc[3] += alpha * v0.w;
        acc[4] += alpha * v1.x; acc[5] += alpha * v1.y;
        acc[6] += alpha * v1.z; acc[7] += alpha * v1.w;
    }
    *(float4*)op = make_float4(acc[0], acc[1], acc[2], acc[3]);
    *(float4*)(op + 4) = make_float4(acc[4], acc[5], acc[6], acc[7]);
}

// ---------------- bias + LayerNorm + (residual) + ELU, warp per row ----------------
__global__ void hg_post_ln(const float* __restrict__ agg, const float* __restrict__ bias,
                           const float* __restrict__ gam, const float* __restrict__ bet,
                           float* __restrict__ h, int residual, int nrows) {
    int warp = (blockIdx.x * blockDim.x + threadIdx.x) >> 5;
    int lane = threadIdx.x & 31;
    if (warp >= nrows) return;
    int c0 = lane * 8;
    const float4* ap = (const float4*)(agg + (long)warp * HD + c0);
    const float4* bp = (const float4*)(bias + c0);
    float4 a0 = ap[0], a1 = ap[1];
    float4 b0 = bp[0], b1 = bp[1];
    float v[8] = {a0.x + b0.x, a0.y + b0.y, a0.z + b0.z, a0.w + b0.w,
                  a1.x + b1.x, a1.y + b1.y, a1.z + b1.z, a1.w + b1.w};
    float sum = 0.f, sq = 0.f;
    #pragma unroll
    for (int j = 0; j < 8; j++) { sum += v[j]; sq += v[j] * v[j]; }
    #pragma unroll
    for (int o = 16; o > 0; o >>= 1) {
        sum += __shfl_xor_sync(0xffffffffu, sum, o);
        sq  += __shfl_xor_sync(0xffffffffu, sq, o);
    }
    float mu = sum * (1.f / HD);
    float var = sq * (1.f / HD) - mu * mu;
    float rstd = rsqrtf(var + LN_EPS);
    const float4* gp = (const float4*)(gam + c0);
    const float4* ep = (const float4*)(bet + c0);
    float4 g0 = gp[0], g1 = gp[1];
    float4 e0 = ep[0], e1 = ep[1];
    float gm[8] = {g0.x, g0.y, g0.z, g0.w, g1.x, g1.y, g1.z, g1.w};
    float bt[8] = {e0.x, e0.y, e0.z, e0.w, e1.x, e1.y, e1.z, e1.w};
    float* hp = h + (long)warp * HD + c0;
    float r[8] = {0.f, 0.f, 0.f, 0.f, 0.f, 0.f, 0.f, 0.f};
    if (residual) {
        float4 r0 = ((const float4*)hp)[0], r1 = ((const float4*)hp)[1];
        r[0] = r0.x; r[1] = r0.y; r[2] = r0.z; r[3] = r0.w;
        r[4] = r1.x; r[5] = r1.y; r[6] = r1.z; r[7] = r1.w;
    }
    float y[8];
    #pragma unroll
    for (int j = 0; j < 8; j++) {
        float t = (v[j] - mu) * rstd * gm[j] + bt[j] + r[j];
        y[j] = t > 0.f ? t : expm1f(t);
    }
    *(float4*)hp = make_float4(y[0], y[1], y[2], y[3]);
    *(float4*)(hp + 4) = make_float4(y[4], y[5], y[6], y[7]);
}

// ---------------- mean pooling addr -> tx (warp per tx node) ----------------
__global__ void hg_pool_mean(const float* __restrict__ haddr, const int* __restrict__ src,
                             const int* __restrict__ rp, const int* __restrict__ eidx,
                             float* __restrict__ out, int ndst) {
    int warp = (blockIdx.x * blockDim.x + threadIdx.x) >> 5;
    int lane = threadIdx.x & 31;
    if (warp >= ndst) return;
    int beg = rp[warp], end = rp[warp + 1];
    int c0 = lane * 8;
    float acc[8] = {0.f, 0.f, 0.f, 0.f, 0.f, 0.f, 0.f, 0.f};
    for (int t = beg; t < end; t++) {
        int s = src[eidx[t]];
        const float4* hp = (const float4*)(haddr + (long)s * HD + c0);
        float4 v0 = hp[0], v1 = hp[1];
        acc[0] += v0.x; acc[1] += v0.y; acc[2] += v0.z; acc[3] += v0.w;
        acc[4] += v1.x; acc[5] += v1.y; acc[6] += v1.z; acc[7] += v1.w;
    }
    int deg = end - beg;
    float inv = 1.f / (float)(deg > 0 ? deg : 1);
    float* op = out + (long)warp * HD + c0;
    *(float4*)op = make_float4(acc[0] * inv, acc[1] * inv, acc[2] * inv, acc[3] * inv);
    *(float4*)(op + 4) = make_float4(acc[4] * inv, acc[5] * inv, acc[6] * inv, acc[7] * inv);
}

// ---------------- host launcher ----------------
#define SYMADDR(p, s) do { void* _t = nullptr; cudaGetSymbolAddress(&_t, s); p = (decltype(p))_t; } while (0)

static inline void launch_gemm(const float* A, const float* B, const float* bias,
                               float* C, int M, int N, int K) {
    dim3 grid((N + BN - 1) / BN, (M + BM - 1) / BM);
    hg_sgemm<<<grid, 256>>>(A, B, bias, C, M, N, K);
}

extern "C" void kernel_launch(void* const* d_in, const int* in_sizes, int n_in,
                              void* d_out, int out_size) {
    const float* x_tx      = (const float*)d_in[0];
    const float* x_addr    = (const float*)d_in[1];
    const int*   addr_idx_at = (const int*)d_in[2];
    const int*   tx_idx_at   = (const int*)d_in[3];
    const int*   tx_idx_ta   = (const int*)d_in[4];
    const int*   addr_idx_ta = (const int*)d_in[5];
    const float* w_in_tx   = (const float*)d_in[6];
    const float* b_in_tx   = (const float*)d_in[7];
    const float* w_in_addr = (const float*)d_in[8];
    const float* b_in_addr = (const float*)d_in[9];
    const float* w_at0 = (const float*)d_in[10];
    const float* as_at0 = (const float*)d_in[11];
    const float* ad_at0 = (const float*)d_in[12];
    const float* b_at0 = (const float*)d_in[13];
    const float* w_ta0 = (const float*)d_in[14];
    const float* as_ta0 = (const float*)d_in[15];
    const float* ad_ta0 = (const float*)d_in[16];
    const float* b_ta0 = (const float*)d_in[17];
    const float* w_at1 = (const float*)d_in[18];
    const float* as_at1 = (const float*)d_in[19];
    const float* ad_at1 = (const float*)d_in[20];
    const float* b_at1 = (const float*)d_in[21];
    const float* w_ta1 = (const float*)d_in[22];
    const float* as_ta1 = (const float*)d_in[23];
    const float* ad_ta1 = (const float*)d_in[24];
    const float* b_ta1 = (const float*)d_in[25];
    const float* ln_g_tx = (const float*)d_in[26];
    const float* ln_b_tx = (const float*)d_in[27];
    const float* ln_g_addr = (const float*)d_in[28];
    const float* ln_b_addr = (const float*)d_in[29];
    const float* w_out = (const float*)d_in[30];
    const float* b_out = (const float*)d_in[31];
    float* out = (float*)d_out;

    float *p_htx64, *p_haddr64, *p_hs_at, *p_hs_ta;
    float *p_agg_tx, *p_agg_addr, *p_htx, *p_haddr;
    float4 *p_als_at, *p_ald_at, *p_als_ta, *p_ald_ta, *p_al_at, *p_al_ta;
    int *p_cnt_tx, *p_cnt_addr, *p_rp_at, *p_rp_ta, *p_cur_tx, *p_cur_addr;
    int *p_eidx_at, *p_eidx_ta, *p_bsum_tx, *p_bsum_addr;
    float *p_ws_at, *p_wd_at, *p_ws_ta, *p_wd_ta;
    SYMADDR(p_htx64, g_htx64);     SYMADDR(p_haddr64, g_haddr64);
    SYMADDR(p_hs_at, g_hs_at);     SYMADDR(p_hs_ta, g_hs_ta);
    SYMADDR(p_agg_tx, g_agg_tx);   SYMADDR(p_agg_addr, g_agg_addr);
    SYMADDR(p_htx, g_htx);         SYMADDR(p_haddr, g_haddr);
    SYMADDR(p_als_at, g_als_at);   SYMADDR(p_ald_at, g_ald_at);
    SYMADDR(p_als_ta, g_als_ta);   SYMADDR(p_ald_ta, g_ald_ta);
    SYMADDR(p_al_at, g_al_at);     SYMADDR(p_al_ta, g_al_ta);
    SYMADDR(p_cnt_tx, g_cnt_tx);   SYMADDR(p_cnt_addr, g_cnt_addr);
    SYMADDR(p_rp_at, g_rp_at);     SYMADDR(p_rp_ta, g_rp_ta);
    SYMADDR(p_cur_tx, g_cur_tx);   SYMADDR(p_cur_addr, g_cur_addr);
    SYMADDR(p_eidx_at, g_eidx_at); SYMADDR(p_eidx_ta, g_eidx_ta);
    SYMADDR(p_bsum_tx, g_bsum_tx); SYMADDR(p_bsum_addr, g_bsum_addr);
    SYMADDR(p_ws_at, g_ws_at);     SYMADDR(p_wd_at, g_wd_at);
    SYMADDR(p_ws_ta, g_ws_ta);     SYMADDR(p_wd_ta, g_wd_ta);

    const int TB = 256;
    const int nb_tx = (N_TX + 1023) / 1024;      // 98
    const int nb_addr = (N_ADDR + 1023) / 1024;  // 196

    // ---- CSR build (shared by both layers + pooling) ----
    hg_zero2<<<(N_ADDR + TB - 1) / TB, TB>>>(p_cnt_tx, N_TX, p_cnt_addr, N_ADDR);
    hg_count<<<(NE + TB - 1) / TB, TB>>>(tx_idx_at, p_cnt_tx, addr_idx_ta, p_cnt_addr);
    hg_scan1<<<nb_tx, 1024>>>(p_cnt_tx, p_rp_at, p_bsum_tx, N_TX);
    hg_scan1<<<nb_addr, 1024>>>(p_cnt_addr, p_rp_ta, p_bsum_addr, N_ADDR);
    hg_scan1<<<1, 1024>>>(p_bsum_tx, p_bsum_tx - 1, nullptr, nb_tx);       // in-place inclusive
    hg_scan1<<<1, 1024>>>(p_bsum_addr, p_bsum_addr - 1, nullptr, nb_addr);
    hg_scan3<<<(N_TX + TB - 1) / TB, TB>>>(p_rp_at, p_bsum_tx, N_TX);
    hg_scan3<<<(N_ADDR + TB - 1) / TB, TB>>>(p_rp_ta, p_bsum_addr, N_ADDR);
    cudaMemcpyAsync(p_cur_tx, p_rp_at, N_TX * sizeof(int), cudaMemcpyDeviceToDevice);
    cudaMemcpyAsync(p_cur_addr, p_rp_ta, N_ADDR * sizeof(int), cudaMemcpyDeviceToDevice);
    hg_fill<<<(NE + TB - 1) / TB, TB>>>(tx_idx_at, p_cur_tx, p_eidx_at,
                                        addr_idx_ta, p_cur_addr, p_eidx_ta);

    // ---- input projections ----
    launch_gemm(x_tx, w_in_tx, b_in_tx, p_htx64, N_TX, HDIM, F_TX);
    launch_gemm(x_addr, w_in_addr, b_in_addr, p_haddr64, N_ADDR, HDIM, F_ADDR);

    int cblk_tx = (N_TX * 32 + TB - 1) / TB;     // warp-per-node grids
    int cblk_addr = (N_ADDR * 32 + TB - 1) / TB;
    int eblk = (NE + TB - 1) / TB;

    for (int layer = 0; layer < 2; layer++) {
        const float* srcA_tx   = layer == 0 ? p_htx64 : p_htx;
        const float* srcA_addr = layer == 0 ? p_haddr64 : p_haddr;
        int K = layer == 0 ? HDIM : HD;
        const float* wa  = layer == 0 ? w_at0 : w_at1;
        const float* asa = layer == 0 ? as_at0 : as_at1;
        const float* ada = layer == 0 ? ad_at0 : ad_at1;
        const float* ba  = layer == 0 ? b_at0 : b_at1;
        const float* wt  = layer == 0 ? w_ta0 : w_ta1;
        const float* ast = layer == 0 ? as_ta0 : as_ta1;
        const float* adt = layer == 0 ? ad_ta0 : ad_ta1;
        const float* bt  = layer == 0 ? b_ta0 : b_ta1;

        // fold attention vectors into W:  Wv[k][h] = sum_c W[k][h*64+c]*a[h][c]
        hg_att_w<<<K, 128>>>(wa, asa, p_ws_at);
        hg_att_w<<<K, 128>>>(wa, ada, p_wd_at);
        hg_att_w<<<K, 128>>>(wt, ast, p_ws_ta);
        hg_att_w<<<K, 128>>>(wt, adt, p_wd_ta);

        // source-side full projections (needed for aggregation)
        launch_gemm(srcA_addr, wa, nullptr, p_hs_at, N_ADDR, HD, K);
        launch_gemm(srcA_tx,   wt, nullptr, p_hs_ta, N_TX,   HD, K);

        // fused attention node coefficients (each node-type read once)
        hg_coef2<<<cblk_addr, TB>>>(srcA_addr, p_ws_at, p_wd_ta, p_als_at, p_ald_ta,
                                    N_ADDR, K);
        hg_coef2<<<cblk_tx,   TB>>>(srcA_tx,   p_wd_at, p_ws_ta, p_ald_at, p_als_ta,
                                    N_TX, K);

        // per-edge logits
        hg_edge_al<<<eblk, TB>>>(addr_idx_at, tx_idx_at, p_als_at, p_ald_at, p_al_at);
        hg_edge_al<<<eblk, TB>>>(tx_idx_ta, addr_idx_ta, p_als_ta, p_ald_ta, p_al_ta);

        // segment softmax + aggregation
        hg_gat_agg<<<cblk_tx, TB>>>(p_hs_at, addr_idx_at, p_al_at, p_rp_at, p_eidx_at,
                                    p_agg_tx, N_TX);
        hg_gat_agg<<<cblk_addr, TB>>>(p_hs_ta, tx_idx_ta, p_al_ta, p_rp_ta, p_eidx_ta,
                                      p_agg_addr, N_ADDR);

        // bias + LN + (residual layer>=1) + ELU -> new h
        hg_post_ln<<<cblk_tx, TB>>>(p_agg_tx, ba, ln_g_tx, ln_b_tx, p_htx,
                                    layer > 0 ? 1 : 0, N_TX);
        hg_post_ln<<<cblk_addr, TB>>>(p_agg_addr, bt, ln_g_addr, ln_b_addr, p_haddr,
                                      layer > 0 ? 1 : 0, N_ADDR);
    }

    // ---- scatter-mean pooling addr -> tx over 'at' edges ----
    hg_pool_mean<<<cblk_tx, TB>>>(p_haddr, addr_idx_at, p_rp_at, p_eidx_at, p_agg_tx, N_TX);

    // ---- output projection ----
    launch_gemm(p_agg_tx, w_out, b_out, out, N_TX, HD, HD);
}

// round 5
// speedup vs baseline: 3.0642x; 1.4615x over previous
#include <cuda_runtime.h>
#include <math.h>

// ---------------- problem constants ----------------
#define N_TX   100000
#define N_ADDR 200000
#define NE     400000
#define F_TX   165
#define F_ADDR 64
#define HDIM   64
#define HD     256
#define LN_EPS 1e-5f
#define NEG_SLOPE 0.2f

// ---------------- scratch (device globals; no cudaMalloc allowed) ----------------
__device__ float g_htx64[(size_t)N_TX * HDIM];
__device__ float g_haddr64[(size_t)N_ADDR * HDIM];
__device__ float g_hs_at[(size_t)N_ADDR * HD];   // addr projected (source side, at)
__device__ float g_hs_ta[(size_t)N_TX * HD];     // tx projected (source side, ta) both layers
__device__ float g_pool_tx[(size_t)N_TX * HD];
__device__ float g_htx[(size_t)N_TX * HD];
__device__ float g_haddr[(size_t)N_ADDR * HD];
__device__ float4 g_als_at[N_ADDR];
__device__ float4 g_ald_at[N_TX];
__device__ float4 g_als_ta[N_TX];
__device__ float4 g_ald_ta[N_ADDR];
__device__ float4 g_al_at[NE];     // csr-ordered logits
__device__ float4 g_al_ta[NE];
__device__ int g_cnt_tx[N_TX];
__device__ int g_cnt_addr[N_ADDR];
__device__ int g_rp_at[N_TX + 1];
__device__ int g_rp_ta[N_ADDR + 1];
__device__ int g_cur_tx[N_TX];
__device__ int g_cur_addr[N_ADDR];
__device__ int g_src_at[NE];       // csr-ordered source node ids
__device__ int g_dst_at[NE];       // csr-ordered dest node ids
__device__ int g_src_ta[NE];
__device__ int g_dst_ta[NE];
__device__ int g_bsum_tx[256];
__device__ int g_bsum_addr[256];
// folded attention weight vectors: Wv[k][head]
__device__ float g_ws_at[HD * 4];
__device__ float g_wd_at[HD * 4];
__device__ float g_ws_ta[HD * 4];
__device__ float g_wd_ta[HD * 4];
__device__ float g_ws_ta1[HD * 4];
__device__ float g_wd_ta1[HD * 4];

// ---------------- packed f32x2 helpers (sm_103a FFMA2 pipe) ----------------
__device__ __forceinline__ unsigned long long hg_pack2(float x, float y) {
    unsigned long long r;
    asm("mov.b64 %0, {%1, %2};" : "=l"(r) : "f"(x), "f"(y));
    return r;
}
__device__ __forceinline__ void hg_unpack2(unsigned long long v, float& x, float& y) {
    asm("mov.b64 {%0, %1}, %2;" : "=f"(x), "=f"(y) : "l"(v));
}
__device__ __forceinline__ void hg_ffma2(unsigned long long& d,
                                         unsigned long long a, unsigned long long b) {
    asm("fma.rn.f32x2 %0, %1, %2, %0;" : "+l"(d) : "l"(a), "l"(b));
}

// ---------------- SGEMM: C[M,N] = A[M,K] @ B[K,N] (+bias) ----------------
#define BM 128
#define BN 128
#define BK 16
#define TM 8
#define TN 8

__global__ __launch_bounds__(256)
void hg_sgemm(const float* __restrict__ A, const float* __restrict__ B,
              const float* __restrict__ bias, float* __restrict__ C,
              int M, int N, int K) {
    __shared__ float As[2][BK][BM];
    __shared__ float Bs[2][BK][BN];
    int tid = threadIdx.x;
    int row0 = blockIdx.y * BM, col0 = blockIdx.x * BN;
    int tx = tid & 15, ty = tid >> 4;
    int arow = tid >> 1, acol = (tid & 1) * 8;
    int brow = tid >> 4, bcol = (tid & 15) * 8;
    bool k4 = ((K & 3) == 0);
    int nk = (K + BK - 1) / BK;

    float ra[8];
    float4 rb0, rb1;

    unsigned long long acc2[TM][TN / 2];
    #pragma unroll
    for (int i = 0; i < TM; i++)
        #pragma unroll
        for (int j = 0; j < TN / 2; j++) acc2[i][j] = 0ull;

    auto loadA = [&](int k0) {
        int gr = row0 + arow;
        if (k4) {
            #pragma unroll
            for (int i = 0; i < 8; i += 4) {
                int gk = k0 + acol + i;
                float4 v = make_float4(0.f, 0.f, 0.f, 0.f);
                if (gr < M && gk < K) v = *(const float4*)(A + (long)gr * K + gk);
                ra[i] = v.x; ra[i + 1] = v.y; ra[i + 2] = v.z; ra[i + 3] = v.w;
            }
        } else {
            #pragma unroll
            for (int i = 0; i < 8; i++) {
                int gk = k0 + acol + i;
                ra[i] = (gr < M && gk < K) ? A[(long)gr * K + gk] : 0.f;
            }
        }
    };
    auto loadB = [&](int k0) {
        int gk = k0 + brow, gn = col0 + bcol;
        rb0 = make_float4(0.f, 0.f, 0.f, 0.f);
        rb1 = rb0;
        if (gk < K && gn < N) {
            rb0 = *(const float4*)(B + (long)gk * N + gn);
            rb1 = *(const float4*)(B + (long)gk * N + gn + 4);
        }
    };
    auto storeA = [&](int s) {
        #pragma unroll
        for (int i = 0; i < 8; i++) As[s][acol + i][arow] = ra[i];
    };
    auto storeB = [&](int s) {
        *(float4*)&Bs[s][brow][bcol] = rb0;
        *(float4*)&Bs[s][brow][bcol + 4] = rb1;
    };

    loadA(0); loadB(0);
    storeA(0); storeB(0);
    __syncthreads();

    int s = 0;
    for (int t = 0; t < nk; t++) {
        if (t + 1 < nk) { loadA((t + 1) * BK); loadB((t + 1) * BK); }
        #pragma unroll
        for (int k = 0; k < BK; k++) {
            float4 a0 = *(float4*)&As[s][k][ty * TM];
            float4 a1 = *(float4*)&As[s][k][ty * TM + 4];
            float4 b0 = *(float4*)&Bs[s][k][tx * TN];
            float4 b1 = *(float4*)&Bs[s][k][tx * TN + 4];
            unsigned long long b2[4];
            b2[0] = hg_pack2(b0.x, b0.y);
            b2[1] = hg_pack2(b0.z, b0.w);
            b2[2] = hg_pack2(b1.x, b1.y);
            b2[3] = hg_pack2(b1.z, b1.w);
            float af[8] = {a0.x, a0.y, a0.z, a0.w, a1.x, a1.y, a1.z, a1.w};
            #pragma unroll
            for (int i = 0; i < TM; i++) {
                unsigned long long a2 = hg_pack2(af[i], af[i]);
                #pragma unroll
                for (int j = 0; j < TN / 2; j++) hg_ffma2(acc2[i][j], a2, b2[j]);
            }
        }
        if (t + 1 < nk) {
            storeA(s ^ 1); storeB(s ^ 1);
            __syncthreads();
            s ^= 1;
        }
    }

    int gc = col0 + tx * TN;
    if (gc >= N) return;
    float bsv[8];
    #pragma unroll
    for (int j = 0; j < 8; j++) bsv[j] = bias ? bias[gc + j] : 0.f;
    #pragma unroll
    for (int i = 0; i < TM; i++) {
        int gr = row0 + ty * TM + i;
        if (gr >= M) continue;
        float acc[8];
        #pragma unroll
        for (int j = 0; j < 4; j++) hg_unpack2(acc2[i][j], acc[2 * j], acc[2 * j + 1]);
        float* cp = C + (long)gr * N + gc;
        *(float4*)cp = make_float4(acc[0] + bsv[0], acc[1] + bsv[1],
                                   acc[2] + bsv[2], acc[3] + bsv[3]);
        *(float4*)(cp + 4) = make_float4(acc[4] + bsv[4], acc[5] + bsv[5],
                                         acc[6] + bsv[6], acc[7] + bsv[7]);
    }
}

// ---------------- CSR build ----------------
__global__ void hg_zero2(int* a, int na, int* b, int nb) {
    int i = blockIdx.x * blockDim.x + threadIdx.x;
    if (i < na) a[i] = 0;
    if (i < nb) b[i] = 0;
}

__global__ void hg_count(const int* __restrict__ dst_at, int* cnt_at,
                         const int* __restrict__ dst_ta, int* cnt_ta) {
    int i = blockIdx.x * blockDim.x + threadIdx.x;
    if (i < NE) {
        atomicAdd(&cnt_at[dst_at[i]], 1);
        atomicAdd(&cnt_ta[dst_ta[i]], 1);
    }
}

__device__ __forceinline__ int hg_warp_incl_scan(int v, int lane) {
    #pragma unroll
    for (int o = 1; o < 32; o <<= 1) {
        int t = __shfl_up_sync(0xffffffffu, v, o);
        if (lane >= o) v += t;
    }
    return v;
}

__global__ void hg_scan1(const int* __restrict__ cnt, int* __restrict__ rp,
                         int* __restrict__ bsum, int n) {
    __shared__ int ws[32];
    int lane = threadIdx.x & 31, wid = threadIdx.x >> 5;
    int i = blockIdx.x * 1024 + threadIdx.x;
    int v = (i < n) ? cnt[i] : 0;
    int s = hg_warp_incl_scan(v, lane);
    if (lane == 31) ws[wid] = s;
    __syncthreads();
    if (wid == 0) {
        int w = ws[lane];
        w = hg_warp_incl_scan(w, lane);
        ws[lane] = w;
    }
    __syncthreads();
    s += (wid ? ws[wid - 1] : 0);
    if (i < n) rp[i + 1] = s;
    if (bsum && threadIdx.x == 1023) bsum[blockIdx.x] = s;
}

__global__ void hg_scan3(int* __restrict__ rp, const int* __restrict__ bsum, int n) {
    int i = blockIdx.x * blockDim.x + threadIdx.x;
    if (i == 0) rp[0] = 0;
    if (i < n) {
        int b = i >> 10;
        if (b > 0) rp[i + 1] += bsum[b - 1];
    }
}

// fill csr with explicit src/dst node ids (no eidx indirection later)
__global__ void hg_fill(const int* __restrict__ s_at, const int* __restrict__ d_at,
                        int* cur_at, int* src_at, int* dst_at,
                        const int* __restrict__ s_ta, const int* __restrict__ d_ta,
                        int* cur_ta, int* src_ta, int* dst_ta) {
    int i = blockIdx.x * blockDim.x + threadIdx.x;
    if (i < NE) {
        int d0 = d_at[i];
        int p = atomicAdd(&cur_at[d0], 1);
        src_at[p] = s_at[i];
        dst_at[p] = d0;
        int d1 = d_ta[i];
        int q = atomicAdd(&cur_ta[d1], 1);
        src_ta[q] = s_ta[i];
        dst_ta[q] = d1;
    }
}

// ---------------- folded attention weights: Wv[k][head] = sum_c W[k][head*64+c]*a[head*64+c] ----------------
__global__ void hg_att_w(const float* __restrict__ W, const float* __restrict__ a,
                         float* __restrict__ Wv) {
    int k = blockIdx.x;
    int head = threadIdx.x >> 5, lane = threadIdx.x & 31;
    const float* wr = W + (long)k * HD + head * 64;
    const float* ar = a + head * 64;
    float s = wr[lane] * ar[lane] + wr[lane + 32] * ar[lane + 32];
    #pragma unroll
    for (int o = 16; o > 0; o >>= 1) s += __shfl_xor_sync(0xffffffffu, s, o);
    if (lane == 0) Wv[k * 4 + head] = s;
}

// ---------------- fused node coefficients (layer-0, from h64) ----------------
__global__ void hg_coef2(const float* __restrict__ x,
                         const float* __restrict__ Wv1, const float* __restrict__ Wv2,
                         float4* __restrict__ out1, float4* __restrict__ out2,
                         int n, int K) {
    int warp = (blockIdx.x * blockDim.x + threadIdx.x) >> 5;
    int lane = threadIdx.x & 31;
    if (warp >= n) return;
    const float* xp = x + (long)warp * K;
    const float4* wv1 = (const float4*)Wv1;
    const float4* wv2 = (const float4*)Wv2;
    float s0 = 0.f, s1 = 0.f, s2 = 0.f, s3 = 0.f;
    float t0 = 0.f, t1 = 0.f, t2 = 0.f, t3 = 0.f;
    for (int k = lane; k < K; k += 32) {
        float xv = xp[k];
        float4 w1 = wv1[k];
        float4 w2 = wv2[k];
        s0 += xv * w1.x; s1 += xv * w1.y; s2 += xv * w1.z; s3 += xv * w1.w;
        t0 += xv * w2.x; t1 += xv * w2.y; t2 += xv * w2.z; t3 += xv * w2.w;
    }
    #pragma unroll
    for (int o = 16; o > 0; o >>= 1) {
        s0 += __shfl_xor_sync(0xffffffffu, s0, o);
        s1 += __shfl_xor_sync(0xffffffffu, s1, o);
        s2 += __shfl_xor_sync(0xffffffffu, s2, o);
        s3 += __shfl_xor_sync(0xffffffffu, s3, o);
        t0 += __shfl_xor_sync(0xffffffffu, t0, o);
        t1 += __shfl_xor_sync(0xffffffffu, t1, o);
        t2 += __shfl_xor_sync(0xffffffffu, t2, o);
        t3 += __shfl_xor_sync(0xffffffffu, t3, o);
    }
    if (lane == 0) {
        out1[warp] = make_float4(s0, s1, s2, s3);
        out2[warp] = make_float4(t0, t1, t2, t3);
    }
}

// ---------------- per-edge logits in CSR order ----------------
__device__ __forceinline__ float hg_leaky(float v) { return v >= 0.f ? v : NEG_SLOPE * v; }

__global__ void hg_edge_al(const int* __restrict__ src, const int* __restrict__ dst,
                           const float4* __restrict__ als, const float4* __restrict__ ald,
                           float4* __restrict__ al) {
    int i = blockIdx.x * blockDim.x + threadIdx.x;
    if (i >= NE) return;
    float4 s = als[src[i]];
    float4 d = ald[dst[i]];
    float4 r;
    r.x = hg_leaky(s.x + d.x);
    r.y = hg_leaky(s.y + d.y);
    r.z = hg_leaky(s.z + d.z);
    r.w = hg_leaky(s.w + d.w);
    al[i] = r;
}

// ---------------- FUSED: segment softmax agg + bias + LN + residual + ELU + next-layer coef ----------------
// warp per dst node; csr-ordered src + al arrays (streaming)
__global__ void hg_gat_agg_ln(const float* __restrict__ hs, const int* __restrict__ srcs,
                              const float4* __restrict__ al, const int* __restrict__ rp,
                              const float* __restrict__ bias, const float* __restrict__ gam,
                              const float* __restrict__ bet, float* __restrict__ h,
                              int residual, const float4* __restrict__ wvn,
                              float4* __restrict__ coef, int ndst) {
    int warp = (blockIdx.x * blockDim.x + threadIdx.x) >> 5;
    int lane = threadIdx.x & 31;
    if (warp >= ndst) return;
    int beg = rp[warp], end = rp[warp + 1];
    int c0 = lane * 8;
    int hl = lane >> 3;  // head index for this lane's 8 channels

    float acc[8] = {0.f, 0.f, 0.f, 0.f, 0.f, 0.f, 0.f, 0.f};
    if (beg < end) {
        float m0 = -3.4e38f, m1 = -3.4e38f, m2 = -3.4e38f, m3 = -3.4e38f;
        for (int t = beg; t < end; t++) {
            float4 a = al[t];
            m0 = fmaxf(m0, a.x); m1 = fmaxf(m1, a.y);
            m2 = fmaxf(m2, a.z); m3 = fmaxf(m3, a.w);
        }
        float d0 = 0.f, d1 = 0.f, d2 = 0.f, d3 = 0.f;
        for (int t = beg; t < end; t++) {
            float4 a = al[t];
            d0 += __expf(a.x - m0); d1 += __expf(a.y - m1);
            d2 += __expf(a.z - m2); d3 += __expf(a.w - m3);
        }
        float mh = (hl & 2) ? ((hl & 1) ? m3 : m2) : ((hl & 1) ? m1 : m0);
        float dh = (hl & 2) ? ((hl & 1) ? d3 : d2) : ((hl & 1) ? d1 : d0);
        float inv = 1.f / dh;
        for (int t = beg; t < end; t++) {
            int sidx = srcs[t];
            float4 a = al[t];
            float av = (hl & 2) ? ((hl & 1) ? a.w : a.z) : ((hl & 1) ? a.y : a.x);
            float alpha = __expf(av - mh) * inv;
            const float4* hp = (const float4*)(hs + (long)sidx * HD + c0);
            float4 v0 = hp[0], v1 = hp[1];
            acc[0] += alpha * v0.x; acc[1] += alpha * v0.y;
            acc[2] += alpha * v0.z; acc[3] += alpha * v0.w;
            acc[4] += alpha * v1.x; acc[5] += alpha * v1.y;
            acc[6] += alpha * v1.z; acc[7] += alpha * v1.w;
        }
    }

    // bias + LN
    const float4* bp = (const float4*)(bias + c0);
    float4 b0 = bp[0], b1 = bp[1];
    float v[8] = {acc[0] + b0.x, acc[1] + b0.y, acc[2] + b0.z, acc[3] + b0.w,
                  acc[4] + b1.x, acc[5] + b1.y, acc[6] + b1.z, acc[7] + b1.w};
    float sum = 0.f, sq = 0.f;
    #pragma unroll
    for (int j = 0; j < 8; j++) { sum += v[j]; sq += v[j] * v[j]; }
    #pragma unroll
    for (int o = 16; o > 0; o >>= 1) {
        sum += __shfl_xor_sync(0xffffffffu, sum, o);
        sq  += __shfl_xor_sync(0xffffffffu, sq, o);
    }
    float mu = sum * (1.f / HD);
    float var = sq * (1.f / HD) - mu * mu;
    float rstd = rsqrtf(var + LN_EPS);

    const float4* gp = (const float4*)(gam + c0);
    const float4* ep = (const float4*)(bet + c0);
    float4 g0 = gp[0], g1 = gp[1];
    float4 e0 = ep[0], e1 = ep[1];
    float gm[8] = {g0.x, g0.y, g0.z, g0.w, g1.x, g1.y, g1.z, g1.w};
    float bt[8] = {e0.x, e0.y, e0.z, e0.w, e1.x, e1.y, e1.z, e1.w};
    float* hp = h + (long)warp * HD + c0;
    float r[8] = {0.f, 0.f, 0.f, 0.f, 0.f, 0.f, 0.f, 0.f};
    if (residual) {
        float4 r0 = ((const float4*)hp)[0], r1 = ((const float4*)hp)[1];
        r[0] = r0.x; r[1] = r0.y; r[2] = r0.z; r[3] = r0.w;
        r[4] = r1.x; r[5] = r1.y; r[6] = r1.z; r[7] = r1.w;
    }
    float y[8];
    #pragma unroll
    for (int j = 0; j < 8; j++) {
        float t = (v[j] - mu) * rstd * gm[j] + bt[j] + r[j];
        y[j] = t > 0.f ? t : expm1f(t);
    }
    *(float4*)hp = make_float4(y[0], y[1], y[2], y[3]);
    *(float4*)(hp + 4) = make_float4(y[4], y[5], y[6], y[7]);

    // next-layer attention coefficient from in-register row: coef[head] = sum_c y[c]*wvn[c][head]
    if (wvn) {
        float p0 = 0.f, p1 = 0.f, p2 = 0.f, p3 = 0.f;
        #pragma unroll
        for (int j = 0; j < 8; j++) {
            float4 w = wvn[c0 + j];
            p0 += y[j] * w.x; p1 += y[j] * w.y; p2 += y[j] * w.z; p3 += y[j] * w.w;
        }
        #pragma unroll
        for (int o = 16; o > 0; o >>= 1) {
            p0 += __shfl_xor_sync(0xffffffffu, p0, o);
            p1 += __shfl_xor_sync(0xffffffffu, p1, o);
            p2 += __shfl_xor_sync(0xffffffffu, p2, o);
            p3 += __shfl_xor_sync(0xffffffffu, p3, o);
        }
        if (lane == 0) coef[warp] = make_float4(p0, p1, p2, p3);
    }
}

// ---------------- mean pooling addr -> tx (warp per tx node) ----------------
__global__ void hg_pool_mean(const float* __restrict__ haddr, const int* __restrict__ srcs,
                             const int* __restrict__ rp, float* __restrict__ out, int ndst) {
    int warp = (blockIdx.x * blockDim.x + threadIdx.x) >> 5;
    int lane = threadIdx.x & 31;
    if (warp >= ndst) return;
    int beg = rp[warp], end = rp[warp + 1];
    int c0 = lane * 8;
    float acc[8] = {0.f, 0.f, 0.f, 0.f, 0.f, 0.f, 0.f, 0.f};
    for (int t = beg; t < end; t++) {
        int s = srcs[t];
        const float4* hp = (const float4*)(haddr + (long)s * HD + c0);
        float4 v0 = hp[0], v1 = hp[1];
        acc[0] += v0.x; acc[1] += v0.y; acc[2] += v0.z; acc[3] += v0.w;
        acc[4] += v1.x; acc[5] += v1.y; acc[6] += v1.z; acc[7] += v1.w;
    }
    int deg = end - beg;
    float inv = 1.f / (float)(deg > 0 ? deg : 1);
    float* op = out + (long)warp * HD + c0;
    *(float4*)op = make_float4(acc[0] * inv, acc[1] * inv, acc[2] * inv, acc[3] * inv);
    *(float4*)(op + 4) = make_float4(acc[4] * inv, acc[5] * inv, acc[6] * inv, acc[7] * inv);
}

// ---------------- host launcher ----------------
#define SYMADDR(p, s) do { void* _t = nullptr; cudaGetSymbolAddress(&_t, s); p = (decltype(p))_t; } while (0)

static inline void launch_gemm(const float* A, const float* B, const float* bias,
                               float* C, int M, int N, int K) {
    dim3 grid((N + BN - 1) / BN, (M + BM - 1) / BM);
    hg_sgemm<<<grid, 256>>>(A, B, bias, C, M, N, K);
}

extern "C" void kernel_launch(void* const* d_in, const int* in_sizes, int n_in,
                              void* d_out, int out_size) {
    const float* x_tx      = (const float*)d_in[0];
    const float* x_addr    = (const float*)d_in[1];
    const int*   addr_idx_at = (const int*)d_in[2];
    const int*   tx_idx_at   = (const int*)d_in[3];
    const int*   tx_idx_ta   = (const int*)d_in[4];
    const int*   addr_idx_ta = (const int*)d_in[5];
    const float* w_in_tx   = (const float*)d_in[6];
    const float* b_in_tx   = (const float*)d_in[7];
    const float* w_in_addr = (const float*)d_in[8];
    const float* b_in_addr = (const float*)d_in[9];
    const float* w_at0 = (const float*)d_in[10];
    const float* as_at0 = (const float*)d_in[11];
    const float* ad_at0 = (const float*)d_in[12];
    const float* b_at0 = (const float*)d_in[13];
    const float* w_ta0 = (const float*)d_in[14];
    const float* as_ta0 = (const float*)d_in[15];
    const float* ad_ta0 = (const float*)d_in[16];
    const float* b_ta0 = (const float*)d_in[17];
    // layer-1 at-relation weights (w_at1/as_at1/ad_at1/b_at1) are dead: h_tx after
    // layer 1 is never used by the reference output.
    const float* w_ta1 = (const float*)d_in[22];
    const float* as_ta1 = (const float*)d_in[23];
    const float* ad_ta1 = (const float*)d_in[24];
    const float* b_ta1 = (const float*)d_in[25];
    const float* ln_g_tx = (const float*)d_in[26];
    const float* ln_b_tx = (const float*)d_in[27];
    const float* ln_g_addr = (const float*)d_in[28];
    const float* ln_b_addr = (const float*)d_in[29];
    const float* w_out = (const float*)d_in[30];
    const float* b_out = (const float*)d_in[31];
    float* out = (float*)d_out;

    float *p_htx64, *p_haddr64, *p_hs_at, *p_hs_ta, *p_pool_tx, *p_htx, *p_haddr;
    float4 *p_als_at, *p_ald_at, *p_als_ta, *p_ald_ta, *p_al_at, *p_al_ta;
    int *p_cnt_tx, *p_cnt_addr, *p_rp_at, *p_rp_ta, *p_cur_tx, *p_cur_addr;
    int *p_src_at, *p_dst_at, *p_src_ta, *p_dst_ta, *p_bsum_tx, *p_bsum_addr;
    float *p_ws_at, *p_wd_at, *p_ws_ta, *p_wd_ta, *p_ws_ta1, *p_wd_ta1;
    SYMADDR(p_htx64, g_htx64);     SYMADDR(p_haddr64, g_haddr64);
    SYMADDR(p_hs_at, g_hs_at);     SYMADDR(p_hs_ta, g_hs_ta);
    SYMADDR(p_pool_tx, g_pool_tx);
    SYMADDR(p_htx, g_htx);         SYMADDR(p_haddr, g_haddr);
    SYMADDR(p_als_at, g_als_at);   SYMADDR(p_ald_at, g_ald_at);
    SYMADDR(p_als_ta, g_als_ta);   SYMADDR(p_ald_ta, g_ald_ta);
    SYMADDR(p_al_at, g_al_at);     SYMADDR(p_al_ta, g_al_ta);
    SYMADDR(p_cnt_tx, g_cnt_tx);   SYMADDR(p_cnt_addr, g_cnt_addr);
    SYMADDR(p_rp_at, g_rp_at);     SYMADDR(p_rp_ta, g_rp_ta);
    SYMADDR(p_cur_tx, g_cur_tx);   SYMADDR(p_cur_addr, g_cur_addr);
    SYMADDR(p_src_at, g_src_at);   SYMADDR(p_dst_at, g_dst_at);
    SYMADDR(p_src_ta, g_src_ta);   SYMADDR(p_dst_ta, g_dst_ta);
    SYMADDR(p_bsum_tx, g_bsum_tx); SYMADDR(p_bsum_addr, g_bsum_addr);
    SYMADDR(p_ws_at, g_ws_at);     SYMADDR(p_wd_at, g_wd_at);
    SYMADDR(p_ws_ta, g_ws_ta);     SYMADDR(p_wd_ta, g_wd_ta);
    SYMADDR(p_ws_ta1, g_ws_ta1);   SYMADDR(p_wd_ta1, g_wd_ta1);

    const int TB = 256;
    const int nb_tx = (N_TX + 1023) / 1024;
    const int nb_addr = (N_ADDR + 1023) / 1024;
    int cblk_tx = (N_TX * 32 + TB - 1) / TB;
    int cblk_addr = (N_ADDR * 32 + TB - 1) / TB;
    int eblk = (NE + TB - 1) / TB;

    // ---- CSR build ----
    hg_zero2<<<(N_ADDR + TB - 1) / TB, TB>>>(p_cnt_tx, N_TX, p_cnt_addr, N_ADDR);
    hg_count<<<(NE + TB - 1) / TB, TB>>>(tx_idx_at, p_cnt_tx, addr_idx_ta, p_cnt_addr);
    hg_scan1<<<nb_tx, 1024>>>(p_cnt_tx, p_rp_at, p_bsum_tx, N_TX);
    hg_scan1<<<nb_addr, 1024>>>(p_cnt_addr, p_rp_ta, p_bsum_addr, N_ADDR);
    hg_scan1<<<1, 1024>>>(p_bsum_tx, p_bsum_tx - 1, nullptr, nb_tx);
    hg_scan1<<<1, 1024>>>(p_bsum_addr, p_bsum_addr - 1, nullptr, nb_addr);
    hg_scan3<<<(N_TX + TB - 1) / TB, TB>>>(p_rp_at, p_bsum_tx, N_TX);
    hg_scan3<<<(N_ADDR + TB - 1) / TB, TB>>>(p_rp_ta, p_bsum_addr, N_ADDR);
    cudaMemcpyAsync(p_cur_tx, p_rp_at, N_TX * sizeof(int), cudaMemcpyDeviceToDevice);
    cudaMemcpyAsync(p_cur_addr, p_rp_ta, N_ADDR * sizeof(int), cudaMemcpyDeviceToDevice);
    hg_fill<<<(NE + TB - 1) / TB, TB>>>(addr_idx_at, tx_idx_at, p_cur_tx, p_src_at, p_dst_at,
                                        tx_idx_ta, addr_idx_ta, p_cur_addr, p_src_ta, p_dst_ta);

    // ---- input projections ----
    launch_gemm(x_tx, w_in_tx, b_in_tx, p_htx64, N_TX, HDIM, F_TX);
    launch_gemm(x_addr, w_in_addr, b_in_addr, p_haddr64, N_ADDR, HDIM, F_ADDR);

    // ---- fold attention weight vectors ----
    hg_att_w<<<HDIM, 128>>>(w_at0, as_at0, p_ws_at);
    hg_att_w<<<HDIM, 128>>>(w_at0, ad_at0, p_wd_at);
    hg_att_w<<<HDIM, 128>>>(w_ta0, as_ta0, p_ws_ta);
    hg_att_w<<<HDIM, 128>>>(w_ta0, ad_ta0, p_wd_ta);
    hg_att_w<<<HD, 128>>>(w_ta1, as_ta1, p_ws_ta1);
    hg_att_w<<<HD, 128>>>(w_ta1, ad_ta1, p_wd_ta1);

    // ---- layer 0 ----
    launch_gemm(p_haddr64, w_at0, nullptr, p_hs_at, N_ADDR, HD, HDIM);
    launch_gemm(p_htx64,   w_ta0, nullptr, p_hs_ta, N_TX,   HD, HDIM);

    hg_coef2<<<cblk_addr, TB>>>(p_haddr64, p_ws_at, p_wd_ta, p_als_at, p_ald_ta,
                                N_ADDR, HDIM);
    hg_coef2<<<cblk_tx,   TB>>>(p_htx64,   p_wd_at, p_ws_ta, p_ald_at, p_als_ta,
                                N_TX, HDIM);

    hg_edge_al<<<eblk, TB>>>(p_src_at, p_dst_at, p_als_at, p_ald_at, p_al_at);
    hg_edge_al<<<eblk, TB>>>(p_src_ta, p_dst_ta, p_als_ta, p_ald_ta, p_al_ta);

    // fused agg+LN+ELU; also emits layer-1 ta coefficients from the fresh rows
    hg_gat_agg_ln<<<cblk_tx, TB>>>(p_hs_at, p_src_at, p_al_at, p_rp_at,
                                   b_at0, ln_g_tx, ln_b_tx, p_htx, 0,
                                   (const float4*)p_ws_ta1, p_als_ta, N_TX);
    hg_gat_agg_ln<<<cblk_addr, TB>>>(p_hs_ta, p_src_ta, p_al_ta, p_rp_ta,
                                     b_ta0, ln_g_addr, ln_b_addr, p_haddr, 0,
                                     (const float4*)p_wd_ta1, p_ald_ta, N_ADDR);

    // ---- layer 1 (ta relation only; tx branch is dead) ----
    launch_gemm(p_htx, w_ta1, nullptr, p_hs_ta, N_TX, HD, HD);

    hg_edge_al<<<eblk, TB>>>(p_src_ta, p_dst_ta, p_als_ta, p_ald_ta, p_al_ta);

    hg_gat_agg_ln<<<cblk_addr, TB>>>(p_hs_ta, p_src_ta, p_al_ta, p_rp_ta,
                                     b_ta1, ln_g_addr, ln_b_addr, p_haddr, 1,
                                     nullptr, nullptr, N_ADDR);

    // ---- scatter-mean pooling addr -> tx over 'at' edges ----
    hg_pool_mean<<<cblk_tx, TB>>>(p_haddr, p_src_at, p_rp_at, p_pool_tx, N_TX);

    // ---- output projection ----
    launch_gemm(p_pool_tx, w_out, b_out, out, N_TX, HD, HD);
}